// round 1
// baseline (speedup 1.0000x reference)
#include <cuda_runtime.h>

#define H 128
#define MAXN 50000
#define MAXE 800000
#define LN_EPS 1e-5f
#define FULLMASK 0xffffffffu

// ---------------- device scratch (no allocations allowed) ----------------
__device__ float g_x[(size_t)MAXN * H];
__device__ float g_agg[(size_t)MAXN * H];
__device__ float g_P[(size_t)MAXN * H];
__device__ float g_Q[(size_t)MAXN * H];
__device__ float g_ew[MAXE];
__device__ int   g_eidx[MAXE];
__device__ int   g_rowptr[MAXN + 1];
__device__ int   g_deg[MAXN];
__device__ int   g_cursor[MAXN];
__device__ int   g_part[256];
__device__ float g_c0[H];

// ---------------- c0 = colsum(Wf[:H]) + bf ----------------
__global__ void c0_kernel(const float* __restrict__ Wf, const float* __restrict__ bf) {
    int j = threadIdx.x;
    float s = bf[j];
    #pragma unroll 8
    for (int i = 0; i < H; i++) s += Wf[i * H + j];
    g_c0[j] = s;
}

// ---------------- x = relu(h_old @ Wf[H:2H] + c0) ----------------
__global__ __launch_bounds__(512) void xinit_kernel(const float* __restrict__ hold,
                                                    const float* __restrict__ Wf, int n) {
    extern __shared__ float sm[];
    float* Ws = sm;            // H*H floats
    float* As = sm + H * H;    // 64*H floats
    const float4* W2 = (const float4*)(Wf + H * H);
    int tid = threadIdx.x;
    for (int i = tid; i < H * H / 4; i += 512) ((float4*)Ws)[i] = W2[i];
    int warp = tid >> 5, lane = tid & 31, c = lane * 4;
    __syncthreads();
    float4 bias = *(const float4*)&g_c0[c];

    for (int tile = blockIdx.x; tile * 64 < n; tile += gridDim.x) {
        int row0 = tile * 64;
        int rows = min(64, n - row0);
        __syncthreads();
        for (int i = tid; i < rows * (H / 4); i += 512)
            ((float4*)As)[i] = ((const float4*)(hold + (size_t)row0 * H))[i];
        __syncthreads();
        int r0 = warp * 4;
        if (r0 < rows) {
            float acc[4][4] = {};
            #pragma unroll 4
            for (int k = 0; k < H; k += 4) {
                float4 w0 = *(float4*)&Ws[(k + 0) * H + c];
                float4 w1 = *(float4*)&Ws[(k + 1) * H + c];
                float4 w2 = *(float4*)&Ws[(k + 2) * H + c];
                float4 w3 = *(float4*)&Ws[(k + 3) * H + c];
                #pragma unroll
                for (int r = 0; r < 4; r++) {
                    float4 a = *(float4*)&As[(r0 + r) * H + k];
                    acc[r][0] += a.x * w0.x + a.y * w1.x + a.z * w2.x + a.w * w3.x;
                    acc[r][1] += a.x * w0.y + a.y * w1.y + a.z * w2.y + a.w * w3.y;
                    acc[r][2] += a.x * w0.z + a.y * w1.z + a.z * w2.z + a.w * w3.z;
                    acc[r][3] += a.x * w0.w + a.y * w1.w + a.z * w2.w + a.w * w3.w;
                }
            }
            #pragma unroll
            for (int r = 0; r < 4; r++) {
                if (r0 + r < rows) {
                    float4 o;
                    o.x = fmaxf(acc[r][0] + bias.x, 0.f);
                    o.y = fmaxf(acc[r][1] + bias.y, 0.f);
                    o.z = fmaxf(acc[r][2] + bias.z, 0.f);
                    o.w = fmaxf(acc[r][3] + bias.w, 0.f);
                    *(float4*)&g_x[(size_t)(row0 + r0 + r) * H + c] = o;
                }
            }
        }
    }
}

// ---------------- ew = sigmoid(relu(A @ We1 + be1) @ We2 + be2) ----------------
__global__ __launch_bounds__(256) void ew_kernel(const float* __restrict__ af,
                                                 const float* __restrict__ We1,
                                                 const float* __restrict__ be1,
                                                 const float* __restrict__ We2,
                                                 const float* __restrict__ be2, int E) {
    __shared__ float W1s[8 * H];
    __shared__ float b1s[H];
    __shared__ float w2s[H];
    int tid = threadIdx.x;
    for (int i = tid; i < 8 * H; i += 256) W1s[i] = We1[i];
    if (tid < H) { b1s[tid] = be1[tid]; w2s[tid] = We2[tid]; }
    __syncthreads();
    int lane = tid & 31, c = lane * 4;
    int warp = (blockIdx.x * 256 + tid) >> 5;
    int nwarp = (gridDim.x * 256) >> 5;
    float b2 = __ldg(be2);
    for (int e = warp; e < E; e += nwarp) {
        const float4* ae = (const float4*)(af + (size_t)e * 8);
        float4 a0 = __ldg(ae), a1 = __ldg(ae + 1);
        float4 acc = *(float4*)&b1s[c];
        float4 w;
        #define EW_STEP(F, AV) \
            w = *(float4*)&W1s[(F) * H + c]; \
            acc.x += (AV) * w.x; acc.y += (AV) * w.y; acc.z += (AV) * w.z; acc.w += (AV) * w.w;
        EW_STEP(0, a0.x) EW_STEP(1, a0.y) EW_STEP(2, a0.z) EW_STEP(3, a0.w)
        EW_STEP(4, a1.x) EW_STEP(5, a1.y) EW_STEP(6, a1.z) EW_STEP(7, a1.w)
        #undef EW_STEP
        acc.x = fmaxf(acc.x, 0.f); acc.y = fmaxf(acc.y, 0.f);
        acc.z = fmaxf(acc.z, 0.f); acc.w = fmaxf(acc.w, 0.f);
        float4 w2 = *(float4*)&w2s[c];
        float p = acc.x * w2.x + acc.y * w2.y + acc.z * w2.z + acc.w * w2.w;
        #pragma unroll
        for (int o = 16; o; o >>= 1) p += __shfl_xor_sync(FULLMASK, p, o);
        if (lane == 0) g_ew[e] = 1.f / (1.f + __expf(-(p + b2)));
    }
}

// ---------------- CSR build ----------------
__global__ void hist_kernel(const int* __restrict__ dst, int E) {
    for (int i = blockIdx.x * blockDim.x + threadIdx.x; i < E; i += gridDim.x * blockDim.x)
        atomicAdd(&g_deg[dst[i]], 1);
}

__global__ void scan1_kernel(int n) {
    __shared__ int s[512];
    int i = blockIdx.x * 512 + threadIdx.x;
    int v = (i < n) ? g_deg[i] : 0;
    s[threadIdx.x] = v;
    __syncthreads();
    for (int off = 1; off < 512; off <<= 1) {
        int t = (threadIdx.x >= off) ? s[threadIdx.x - off] : 0;
        __syncthreads();
        s[threadIdx.x] += t;
        __syncthreads();
    }
    if (i < n) g_rowptr[i + 1] = s[threadIdx.x];
    if (threadIdx.x == 511) g_part[blockIdx.x] = s[511];
    if (i == 0) g_rowptr[0] = 0;
}

__global__ void scan2_kernel(int nb) {
    __shared__ int s[256];
    int v = (threadIdx.x < nb) ? g_part[threadIdx.x] : 0;
    s[threadIdx.x] = v;
    __syncthreads();
    for (int off = 1; off < 256; off <<= 1) {
        int t = (threadIdx.x >= off) ? s[threadIdx.x - off] : 0;
        __syncthreads();
        s[threadIdx.x] += t;
        __syncthreads();
    }
    if (threadIdx.x < nb) g_part[threadIdx.x] = s[threadIdx.x] - v;  // exclusive
}

__global__ void scan3_kernel(int n) {
    for (int i = blockIdx.x * blockDim.x + threadIdx.x; i < n; i += gridDim.x * blockDim.x)
        g_rowptr[i + 1] += g_part[i >> 9];
}

__global__ void fill_kernel(const int* __restrict__ dst, int E) {
    for (int i = blockIdx.x * blockDim.x + threadIdx.x; i < E; i += gridDim.x * blockDim.x) {
        int d = dst[i];
        int p = atomicAdd(&g_cursor[d], 1);
        g_eidx[g_rowptr[d] + p] = i;
    }
}

// ---------------- agg[i] = sum_{e: dst=i} ew[e] * x[src[e]] (atomic-free) ----------------
__global__ __launch_bounds__(256) void gather_kernel(const int* __restrict__ src, int n) {
    int lane = threadIdx.x & 31, c = lane * 4;
    int warp = (blockIdx.x * 256 + threadIdx.x) >> 5;
    int nwarp = (gridDim.x * 256) >> 5;
    for (int node = warp; node < n; node += nwarp) {
        int b = g_rowptr[node], e = g_rowptr[node + 1];
        float4 acc = {0.f, 0.f, 0.f, 0.f};
        for (int t = b; t < e; t++) {
            int ed = g_eidx[t];
            float w = g_ew[ed];
            int s = src[ed];
            float4 v = *(const float4*)&g_x[(size_t)s * H + c];
            acc.x += w * v.x; acc.y += w * v.y; acc.z += w * v.z; acc.w += w * v.w;
        }
        *(float4*)&g_agg[(size_t)node * H + c] = acc;
    }
}

// ---------------- x = relu(LN(agg@Wrel + brel + x@Wroot)) + x ----------------
__global__ __launch_bounds__(512) void layer_kernel(const float* __restrict__ Wrel,
                                                    const float* __restrict__ brel,
                                                    const float* __restrict__ Wroot,
                                                    const float* __restrict__ gamma,
                                                    const float* __restrict__ beta, int n) {
    extern __shared__ float sm[];
    float* W1s = sm;                 // H*H
    float* W2s = sm + H * H;         // H*H
    float* As  = sm + 2 * H * H;     // 64*H (agg tile)
    float* Xs  = sm + 2 * H * H + 64 * H;  // 64*H (x tile)
    int tid = threadIdx.x;
    for (int i = tid; i < H * H / 4; i += 512) {
        ((float4*)W1s)[i] = ((const float4*)Wrel)[i];
        ((float4*)W2s)[i] = ((const float4*)Wroot)[i];
    }
    int warp = tid >> 5, lane = tid & 31, c = lane * 4;
    __syncthreads();
    float4 bias = *(const float4*)&brel[c];
    float4 g4   = *(const float4*)&gamma[c];
    float4 b4   = *(const float4*)&beta[c];

    for (int tile = blockIdx.x; tile * 64 < n; tile += gridDim.x) {
        int row0 = tile * 64;
        int rows = min(64, n - row0);
        __syncthreads();
        for (int i = tid; i < rows * (H / 4); i += 512) {
            ((float4*)As)[i] = ((const float4*)(g_agg + (size_t)row0 * H))[i];
            ((float4*)Xs)[i] = ((const float4*)(g_x + (size_t)row0 * H))[i];
        }
        __syncthreads();
        int r0 = warp * 4;
        if (r0 < rows) {
            float acc[4][4] = {};
            #pragma unroll 2
            for (int k = 0; k < H; k += 4) {
                float4 u0 = *(float4*)&W1s[(k + 0) * H + c];
                float4 u1 = *(float4*)&W1s[(k + 1) * H + c];
                float4 u2 = *(float4*)&W1s[(k + 2) * H + c];
                float4 u3 = *(float4*)&W1s[(k + 3) * H + c];
                float4 v0 = *(float4*)&W2s[(k + 0) * H + c];
                float4 v1 = *(float4*)&W2s[(k + 1) * H + c];
                float4 v2 = *(float4*)&W2s[(k + 2) * H + c];
                float4 v3 = *(float4*)&W2s[(k + 3) * H + c];
                #pragma unroll
                for (int r = 0; r < 4; r++) {
                    float4 a = *(float4*)&As[(r0 + r) * H + k];
                    float4 x = *(float4*)&Xs[(r0 + r) * H + k];
                    acc[r][0] += a.x * u0.x + a.y * u1.x + a.z * u2.x + a.w * u3.x
                               + x.x * v0.x + x.y * v1.x + x.z * v2.x + x.w * v3.x;
                    acc[r][1] += a.x * u0.y + a.y * u1.y + a.z * u2.y + a.w * u3.y
                               + x.x * v0.y + x.y * v1.y + x.z * v2.y + x.w * v3.y;
                    acc[r][2] += a.x * u0.z + a.y * u1.z + a.z * u2.z + a.w * u3.z
                               + x.x * v0.z + x.y * v1.z + x.z * v2.z + x.w * v3.z;
                    acc[r][3] += a.x * u0.w + a.y * u1.w + a.z * u2.w + a.w * u3.w
                               + x.x * v0.w + x.y * v1.w + x.z * v2.w + x.w * v3.w;
                }
            }
            #pragma unroll
            for (int r = 0; r < 4; r++) {
                int row = r0 + r;
                if (row < rows) {
                    float v0 = acc[r][0] + bias.x;
                    float v1 = acc[r][1] + bias.y;
                    float v2 = acc[r][2] + bias.z;
                    float v3 = acc[r][3] + bias.w;
                    float s = v0 + v1 + v2 + v3;
                    #pragma unroll
                    for (int o = 16; o; o >>= 1) s += __shfl_xor_sync(FULLMASK, s, o);
                    float mean = s * (1.f / H);
                    float d0 = v0 - mean, d1 = v1 - mean, d2 = v2 - mean, d3 = v3 - mean;
                    float ss = d0 * d0 + d1 * d1 + d2 * d2 + d3 * d3;
                    #pragma unroll
                    for (int o = 16; o; o >>= 1) ss += __shfl_xor_sync(FULLMASK, ss, o);
                    float rstd = rsqrtf(ss * (1.f / H) + LN_EPS);
                    float4 xr = *(float4*)&Xs[row * H + c];
                    float4 o4;
                    o4.x = fmaxf(d0 * rstd * g4.x + b4.x, 0.f) + xr.x;
                    o4.y = fmaxf(d1 * rstd * g4.y + b4.y, 0.f) + xr.y;
                    o4.z = fmaxf(d2 * rstd * g4.z + b4.z, 0.f) + xr.z;
                    o4.w = fmaxf(d3 * rstd * g4.w + b4.w, 0.f) + xr.w;
                    *(float4*)&g_x[(size_t)(row0 + row) * H + c] = o4;
                }
            }
        }
    }
}

// ---------------- P = x @ Wd1[0:H], Q = x @ Wd1[H:2H] ----------------
__global__ __launch_bounds__(512) void pq_kernel(const float* __restrict__ Wd1, int n) {
    extern __shared__ float sm[];
    float* W1s = sm;
    float* W2s = sm + H * H;
    float* Xs  = sm + 2 * H * H;   // 64*H
    int tid = threadIdx.x;
    for (int i = tid; i < H * H / 4; i += 512) {
        ((float4*)W1s)[i] = ((const float4*)Wd1)[i];
        ((float4*)W2s)[i] = ((const float4*)(Wd1 + H * H))[i];
    }
    int warp = tid >> 5, lane = tid & 31, c = lane * 4;
    __syncthreads();
    for (int tile = blockIdx.x; tile * 64 < n; tile += gridDim.x) {
        int row0 = tile * 64;
        int rows = min(64, n - row0);
        __syncthreads();
        for (int i = tid; i < rows * (H / 4); i += 512)
            ((float4*)Xs)[i] = ((const float4*)(g_x + (size_t)row0 * H))[i];
        __syncthreads();
        int r0 = warp * 4;
        if (r0 < rows) {
            float ap[4][4] = {};
            float aq[4][4] = {};
            for (int k = 0; k < H; k += 4) {
                float4 u0 = *(float4*)&W1s[(k + 0) * H + c];
                float4 u1 = *(float4*)&W1s[(k + 1) * H + c];
                float4 u2 = *(float4*)&W1s[(k + 2) * H + c];
                float4 u3 = *(float4*)&W1s[(k + 3) * H + c];
                float4 v0 = *(float4*)&W2s[(k + 0) * H + c];
                float4 v1 = *(float4*)&W2s[(k + 1) * H + c];
                float4 v2 = *(float4*)&W2s[(k + 2) * H + c];
                float4 v3 = *(float4*)&W2s[(k + 3) * H + c];
                #pragma unroll
                for (int r = 0; r < 4; r++) {
                    float4 a = *(float4*)&Xs[(r0 + r) * H + k];
                    ap[r][0] += a.x * u0.x + a.y * u1.x + a.z * u2.x + a.w * u3.x;
                    ap[r][1] += a.x * u0.y + a.y * u1.y + a.z * u2.y + a.w * u3.y;
                    ap[r][2] += a.x * u0.z + a.y * u1.z + a.z * u2.z + a.w * u3.z;
                    ap[r][3] += a.x * u0.w + a.y * u1.w + a.z * u2.w + a.w * u3.w;
                    aq[r][0] += a.x * v0.x + a.y * v1.x + a.z * v2.x + a.w * v3.x;
                    aq[r][1] += a.x * v0.y + a.y * v1.y + a.z * v2.y + a.w * v3.y;
                    aq[r][2] += a.x * v0.z + a.y * v1.z + a.z * v2.z + a.w * v3.z;
                    aq[r][3] += a.x * v0.w + a.y * v1.w + a.z * v2.w + a.w * v3.w;
                }
            }
            #pragma unroll
            for (int r = 0; r < 4; r++) {
                int row = r0 + r;
                if (row < rows) {
                    size_t off = (size_t)(row0 + row) * H + c;
                    float4 p = {ap[r][0], ap[r][1], ap[r][2], ap[r][3]};
                    float4 q = {aq[r][0], aq[r][1], aq[r][2], aq[r][3]};
                    *(float4*)&g_P[off] = p;
                    *(float4*)&g_Q[off] = q;
                }
            }
        }
    }
}

// ---------------- out[e] = relu(P[src]+Q[dst]+A@Wd1_tail+bd1) @ Wd2 + bd2 ----------------
__global__ __launch_bounds__(256) void decoder_kernel(const int* __restrict__ src,
                                                      const int* __restrict__ dst,
                                                      const float* __restrict__ af,
                                                      const float* __restrict__ Wd1,
                                                      const float* __restrict__ bd1,
                                                      const float* __restrict__ Wd2,
                                                      const float* __restrict__ bd2,
                                                      float* __restrict__ out, int E) {
    __shared__ float Wt[8 * H];
    __shared__ float b1s[H];
    __shared__ float w2s[H];
    int tid = threadIdx.x;
    const float* Wtail = Wd1 + 2 * H * H;
    for (int i = tid; i < 8 * H; i += 256) Wt[i] = Wtail[i];
    if (tid < H) { b1s[tid] = bd1[tid]; w2s[tid] = Wd2[tid]; }
    __syncthreads();
    int lane = tid & 31, c = lane * 4;
    int warp = (blockIdx.x * 256 + tid) >> 5;
    int nwarp = (gridDim.x * 256) >> 5;
    float b2 = __ldg(bd2);
    for (int e = warp; e < E; e += nwarp) {
        int s = src[e], d = dst[e];
        float4 p = *(const float4*)&g_P[(size_t)s * H + c];
        float4 q = *(const float4*)&g_Q[(size_t)d * H + c];
        const float4* ae = (const float4*)(af + (size_t)e * 8);
        float4 a0 = __ldg(ae), a1 = __ldg(ae + 1);
        float4 b1 = *(float4*)&b1s[c];
        float h0 = p.x + q.x + b1.x, h1 = p.y + q.y + b1.y;
        float h2 = p.z + q.z + b1.z, h3 = p.w + q.w + b1.w;
        float4 w;
        #define DEC_STEP(F, AV) \
            w = *(float4*)&Wt[(F) * H + c]; \
            h0 += (AV) * w.x; h1 += (AV) * w.y; h2 += (AV) * w.z; h3 += (AV) * w.w;
        DEC_STEP(0, a0.x) DEC_STEP(1, a0.y) DEC_STEP(2, a0.z) DEC_STEP(3, a0.w)
        DEC_STEP(4, a1.x) DEC_STEP(5, a1.y) DEC_STEP(6, a1.z) DEC_STEP(7, a1.w)
        #undef DEC_STEP
        h0 = fmaxf(h0, 0.f); h1 = fmaxf(h1, 0.f); h2 = fmaxf(h2, 0.f); h3 = fmaxf(h3, 0.f);
        float4 w2 = *(float4*)&w2s[c];
        float part = h0 * w2.x + h1 * w2.y + h2 * w2.z + h3 * w2.w;
        #pragma unroll
        for (int o = 16; o; o >>= 1) part += __shfl_xor_sync(FULLMASK, part, o);
        if (lane == 0) out[e] = part + b2;
    }
}

// ---------------- launch ----------------
extern "C" void kernel_launch(void* const* d_in, const int* in_sizes, int n_in,
                              void* d_out, int out_size) {
    const int*   ei   = (const int*)d_in[0];
    const float* af   = (const float*)d_in[1];
    const float* hold = (const float*)d_in[2];
    int E = in_sizes[0] / 2;
    int n = in_sizes[2] / H;
    if (E > MAXE) E = MAXE;
    if (n > MAXN) n = MAXN;

    int pi = (n_in >= 19) ? 4 : 3;  // skip num_nodes scalar if present
    const float* Wf    = (const float*)d_in[pi + 0];
    const float* bf    = (const float*)d_in[pi + 1];
    const float* We1   = (const float*)d_in[pi + 2];
    const float* be1   = (const float*)d_in[pi + 3];
    const float* We2   = (const float*)d_in[pi + 4];
    const float* be2   = (const float*)d_in[pi + 5];
    const float* Wrel  = (const float*)d_in[pi + 6];
    const float* brel  = (const float*)d_in[pi + 7];
    const float* Wroot = (const float*)d_in[pi + 8];
    const float* gamma = (const float*)d_in[pi + 9];
    const float* beta  = (const float*)d_in[pi + 10];
    const float* Wd1   = (const float*)d_in[pi + 11];
    const float* bd1   = (const float*)d_in[pi + 12];
    const float* Wd2   = (const float*)d_in[pi + 13];
    const float* bd2   = (const float*)d_in[pi + 14];

    const int* src = ei;
    const int* dst = ei + E;

    size_t smem_xinit = (size_t)(H * H + 64 * H) * sizeof(float);          // 96 KB
    size_t smem_layer = (size_t)(2 * H * H + 2 * 64 * H) * sizeof(float);  // 192 KB
    size_t smem_pq    = (size_t)(2 * H * H + 64 * H) * sizeof(float);      // 160 KB
    cudaFuncSetAttribute(xinit_kernel, cudaFuncAttributeMaxDynamicSharedMemorySize, (int)smem_xinit);
    cudaFuncSetAttribute(layer_kernel, cudaFuncAttributeMaxDynamicSharedMemorySize, (int)smem_layer);
    cudaFuncSetAttribute(pq_kernel, cudaFuncAttributeMaxDynamicSharedMemorySize, (int)smem_pq);

    void *degp = nullptr, *curp = nullptr;
    cudaGetSymbolAddress(&degp, g_deg);
    cudaGetSymbolAddress(&curp, g_cursor);
    cudaMemsetAsync(degp, 0, (size_t)n * sizeof(int), 0);
    cudaMemsetAsync(curp, 0, (size_t)n * sizeof(int), 0);

    c0_kernel<<<1, H>>>(Wf, bf);
    xinit_kernel<<<148, 512, smem_xinit>>>(hold, Wf, n);
    ew_kernel<<<2048, 256>>>(af, We1, be1, We2, be2, E);

    // CSR build (by dst)
    hist_kernel<<<1024, 256>>>(dst, E);
    int nb = (n + 511) / 512;
    scan1_kernel<<<nb, 512>>>(n);
    scan2_kernel<<<1, 256>>>(nb);
    scan3_kernel<<<256, 256>>>(n);
    fill_kernel<<<1024, 256>>>(dst, E);

    for (int l = 0; l < 3; l++) {
        gather_kernel<<<6250, 256>>>(src, n);
        layer_kernel<<<148, 512, smem_layer>>>(Wrel + (size_t)l * H * H, brel + (size_t)l * H,
                                               Wroot + (size_t)l * H * H, gamma + (size_t)l * H,
                                               beta + (size_t)l * H, n);
    }

    pq_kernel<<<148, 512, smem_pq>>>(Wd1, n);
    decoder_kernel<<<2048, 256>>>(src, dst, af, Wd1, bd1, Wd2, bd2, (float*)d_out, E);
}

// round 2
// speedup vs baseline: 1.0130x; 1.0130x over previous
#include <cuda_runtime.h>

#define H 128
#define MAXN 50000
#define MAXE 800000
#define LN_EPS 1e-5f
#define FULLMASK 0xffffffffu

// ---------------- device scratch (no allocations allowed) ----------------
__device__ float g_x[(size_t)MAXN * H];
__device__ float g_agg[(size_t)MAXN * H];
__device__ float g_P[(size_t)MAXN * H];
__device__ float g_Q[(size_t)MAXN * H];
__device__ float g_ew[MAXE];
__device__ int   g_srcs[MAXE];   // dst-sorted src ids   (payload CSR)
__device__ float g_ews[MAXE];    // dst-sorted edge weights
__device__ int   g_rowptr[MAXN + 1];
__device__ int   g_deg[MAXN];
__device__ int   g_cursor[MAXN];
__device__ int   g_part[256];
__device__ float g_c0[H];

// ---------------- c0 = colsum(Wf[:H]) + bf ----------------
__global__ void c0_kernel(const float* __restrict__ Wf, const float* __restrict__ bf) {
    int j = threadIdx.x;
    float s = bf[j];
    #pragma unroll 8
    for (int i = 0; i < H; i++) s += Wf[i * H + j];
    g_c0[j] = s;
}

// ---------------- x = relu(h_old @ Wf[H:2H] + c0) ----------------
__global__ __launch_bounds__(512) void xinit_kernel(const float* __restrict__ hold,
                                                    const float* __restrict__ Wf, int n) {
    extern __shared__ float sm[];
    float* Ws = sm;            // H*H floats
    float* As = sm + H * H;    // 64*H floats
    const float4* W2 = (const float4*)(Wf + H * H);
    int tid = threadIdx.x;
    for (int i = tid; i < H * H / 4; i += 512) ((float4*)Ws)[i] = W2[i];
    int warp = tid >> 5, lane = tid & 31, c = lane * 4;
    __syncthreads();
    float4 bias = *(const float4*)&g_c0[c];

    for (int tile = blockIdx.x; tile * 64 < n; tile += gridDim.x) {
        int row0 = tile * 64;
        int rows = min(64, n - row0);
        __syncthreads();
        for (int i = tid; i < rows * (H / 4); i += 512)
            ((float4*)As)[i] = ((const float4*)(hold + (size_t)row0 * H))[i];
        __syncthreads();
        int r0 = warp * 4;
        if (r0 < rows) {
            float acc[4][4] = {};
            #pragma unroll 4
            for (int k = 0; k < H; k += 4) {
                float4 w0 = *(float4*)&Ws[(k + 0) * H + c];
                float4 w1 = *(float4*)&Ws[(k + 1) * H + c];
                float4 w2 = *(float4*)&Ws[(k + 2) * H + c];
                float4 w3 = *(float4*)&Ws[(k + 3) * H + c];
                #pragma unroll
                for (int r = 0; r < 4; r++) {
                    float4 a = *(float4*)&As[(r0 + r) * H + k];
                    acc[r][0] += a.x * w0.x + a.y * w1.x + a.z * w2.x + a.w * w3.x;
                    acc[r][1] += a.x * w0.y + a.y * w1.y + a.z * w2.y + a.w * w3.y;
                    acc[r][2] += a.x * w0.z + a.y * w1.z + a.z * w2.z + a.w * w3.z;
                    acc[r][3] += a.x * w0.w + a.y * w1.w + a.z * w2.w + a.w * w3.w;
                }
            }
            #pragma unroll
            for (int r = 0; r < 4; r++) {
                if (r0 + r < rows) {
                    float4 o;
                    o.x = fmaxf(acc[r][0] + bias.x, 0.f);
                    o.y = fmaxf(acc[r][1] + bias.y, 0.f);
                    o.z = fmaxf(acc[r][2] + bias.z, 0.f);
                    o.w = fmaxf(acc[r][3] + bias.w, 0.f);
                    *(float4*)&g_x[(size_t)(row0 + r0 + r) * H + c] = o;
                }
            }
        }
    }
}

// ---------------- ew = sigmoid(relu(A @ We1 + be1) @ We2 + be2) ----------------
__global__ __launch_bounds__(256) void ew_kernel(const float* __restrict__ af,
                                                 const float* __restrict__ We1,
                                                 const float* __restrict__ be1,
                                                 const float* __restrict__ We2,
                                                 const float* __restrict__ be2, int E) {
    __shared__ float W1s[8 * H];
    __shared__ float b1s[H];
    __shared__ float w2s[H];
    int tid = threadIdx.x;
    for (int i = tid; i < 8 * H; i += 256) W1s[i] = We1[i];
    if (tid < H) { b1s[tid] = be1[tid]; w2s[tid] = We2[tid]; }
    __syncthreads();
    int lane = tid & 31, c = lane * 4;
    int warp = (blockIdx.x * 256 + tid) >> 5;
    int nwarp = (gridDim.x * 256) >> 5;
    float b2 = __ldg(be2);
    for (int e = warp; e < E; e += nwarp) {
        const float4* ae = (const float4*)(af + (size_t)e * 8);
        float4 a0 = __ldg(ae), a1 = __ldg(ae + 1);
        float4 acc = *(float4*)&b1s[c];
        float4 w;
        #define EW_STEP(F, AV) \
            w = *(float4*)&W1s[(F) * H + c]; \
            acc.x += (AV) * w.x; acc.y += (AV) * w.y; acc.z += (AV) * w.z; acc.w += (AV) * w.w;
        EW_STEP(0, a0.x) EW_STEP(1, a0.y) EW_STEP(2, a0.z) EW_STEP(3, a0.w)
        EW_STEP(4, a1.x) EW_STEP(5, a1.y) EW_STEP(6, a1.z) EW_STEP(7, a1.w)
        #undef EW_STEP
        acc.x = fmaxf(acc.x, 0.f); acc.y = fmaxf(acc.y, 0.f);
        acc.z = fmaxf(acc.z, 0.f); acc.w = fmaxf(acc.w, 0.f);
        float4 w2 = *(float4*)&w2s[c];
        float p = acc.x * w2.x + acc.y * w2.y + acc.z * w2.z + acc.w * w2.w;
        #pragma unroll
        for (int o = 16; o; o >>= 1) p += __shfl_xor_sync(FULLMASK, p, o);
        if (lane == 0) g_ew[e] = 1.f / (1.f + __expf(-(p + b2)));
    }
}

// ---------------- CSR build ----------------
__global__ void hist_kernel(const int* __restrict__ dst, int E) {
    for (int i = blockIdx.x * blockDim.x + threadIdx.x; i < E; i += gridDim.x * blockDim.x)
        atomicAdd(&g_deg[dst[i]], 1);
}

__global__ void scan1_kernel(int n) {
    __shared__ int s[512];
    int i = blockIdx.x * 512 + threadIdx.x;
    int v = (i < n) ? g_deg[i] : 0;
    s[threadIdx.x] = v;
    __syncthreads();
    for (int off = 1; off < 512; off <<= 1) {
        int t = (threadIdx.x >= off) ? s[threadIdx.x - off] : 0;
        __syncthreads();
        s[threadIdx.x] += t;
        __syncthreads();
    }
    if (i < n) g_rowptr[i + 1] = s[threadIdx.x];
    if (threadIdx.x == 511) g_part[blockIdx.x] = s[511];
    if (i == 0) g_rowptr[0] = 0;
}

__global__ void scan2_kernel(int nb) {
    __shared__ int s[256];
    int v = (threadIdx.x < nb) ? g_part[threadIdx.x] : 0;
    s[threadIdx.x] = v;
    __syncthreads();
    for (int off = 1; off < 256; off <<= 1) {
        int t = (threadIdx.x >= off) ? s[threadIdx.x - off] : 0;
        __syncthreads();
        s[threadIdx.x] += t;
        __syncthreads();
    }
    if (threadIdx.x < nb) g_part[threadIdx.x] = s[threadIdx.x] - v;  // exclusive
}

__global__ void scan3_kernel(int n) {
    for (int i = blockIdx.x * blockDim.x + threadIdx.x; i < n; i += gridDim.x * blockDim.x)
        g_rowptr[i + 1] += g_part[i >> 9];
}

// fill: scatter (src, ew) payload into dst-sorted CSR order
__global__ void fill_kernel(const int* __restrict__ src, const int* __restrict__ dst, int E) {
    for (int i = blockIdx.x * blockDim.x + threadIdx.x; i < E; i += gridDim.x * blockDim.x) {
        int d = dst[i];
        int p = atomicAdd(&g_cursor[d], 1);
        int pos = g_rowptr[d] + p;
        g_srcs[pos] = src[i];
        g_ews[pos]  = g_ew[i];
    }
}

// ---------------- agg[i] = sum_{e: dst=i} ew[e] * x[src[e]] (atomic-free, MLP=4) ----------------
__global__ __launch_bounds__(256) void gather_kernel(int n) {
    int lane = threadIdx.x & 31, c = lane * 4;
    int warp = (blockIdx.x * 256 + threadIdx.x) >> 5;
    int nwarp = (gridDim.x * 256) >> 5;
    for (int node = warp; node < n; node += nwarp) {
        int b = __ldg(&g_rowptr[node]), e = __ldg(&g_rowptr[node + 1]);
        float4 acc = {0.f, 0.f, 0.f, 0.f};
        int t = b;
        for (; t + 4 <= e; t += 4) {
            // batch the metadata loads (contiguous, uniform) then 4 independent row loads
            int s0 = __ldg(&g_srcs[t + 0]), s1 = __ldg(&g_srcs[t + 1]);
            int s2 = __ldg(&g_srcs[t + 2]), s3 = __ldg(&g_srcs[t + 3]);
            float w0 = __ldg(&g_ews[t + 0]), w1 = __ldg(&g_ews[t + 1]);
            float w2 = __ldg(&g_ews[t + 2]), w3 = __ldg(&g_ews[t + 3]);
            float4 v0 = __ldg((const float4*)&g_x[(size_t)s0 * H + c]);
            float4 v1 = __ldg((const float4*)&g_x[(size_t)s1 * H + c]);
            float4 v2 = __ldg((const float4*)&g_x[(size_t)s2 * H + c]);
            float4 v3 = __ldg((const float4*)&g_x[(size_t)s3 * H + c]);
            acc.x += w0 * v0.x; acc.y += w0 * v0.y; acc.z += w0 * v0.z; acc.w += w0 * v0.w;
            acc.x += w1 * v1.x; acc.y += w1 * v1.y; acc.z += w1 * v1.z; acc.w += w1 * v1.w;
            acc.x += w2 * v2.x; acc.y += w2 * v2.y; acc.z += w2 * v2.z; acc.w += w2 * v2.w;
            acc.x += w3 * v3.x; acc.y += w3 * v3.y; acc.z += w3 * v3.z; acc.w += w3 * v3.w;
        }
        for (; t < e; t++) {
            int s = __ldg(&g_srcs[t]);
            float w = __ldg(&g_ews[t]);
            float4 v = __ldg((const float4*)&g_x[(size_t)s * H + c]);
            acc.x += w * v.x; acc.y += w * v.y; acc.z += w * v.z; acc.w += w * v.w;
        }
        *(float4*)&g_agg[(size_t)node * H + c] = acc;
    }
}

// ---------------- x = relu(LN(agg@Wrel + brel + x@Wroot)) + x ----------------
__global__ __launch_bounds__(512) void layer_kernel(const float* __restrict__ Wrel,
                                                    const float* __restrict__ brel,
                                                    const float* __restrict__ Wroot,
                                                    const float* __restrict__ gamma,
                                                    const float* __restrict__ beta, int n) {
    extern __shared__ float sm[];
    float* W1s = sm;                 // H*H
    float* W2s = sm + H * H;         // H*H
    float* As  = sm + 2 * H * H;     // 64*H (agg tile)
    float* Xs  = sm + 2 * H * H + 64 * H;  // 64*H (x tile)
    int tid = threadIdx.x;
    for (int i = tid; i < H * H / 4; i += 512) {
        ((float4*)W1s)[i] = ((const float4*)Wrel)[i];
        ((float4*)W2s)[i] = ((const float4*)Wroot)[i];
    }
    int warp = tid >> 5, lane = tid & 31, c = lane * 4;
    __syncthreads();
    float4 bias = *(const float4*)&brel[c];
    float4 g4   = *(const float4*)&gamma[c];
    float4 b4   = *(const float4*)&beta[c];

    for (int tile = blockIdx.x; tile * 64 < n; tile += gridDim.x) {
        int row0 = tile * 64;
        int rows = min(64, n - row0);
        __syncthreads();
        for (int i = tid; i < rows * (H / 4); i += 512) {
            ((float4*)As)[i] = ((const float4*)(g_agg + (size_t)row0 * H))[i];
            ((float4*)Xs)[i] = ((const float4*)(g_x + (size_t)row0 * H))[i];
        }
        __syncthreads();
        int r0 = warp * 4;
        if (r0 < rows) {
            float acc[4][4] = {};
            #pragma unroll 2
            for (int k = 0; k < H; k += 4) {
                float4 u0 = *(float4*)&W1s[(k + 0) * H + c];
                float4 u1 = *(float4*)&W1s[(k + 1) * H + c];
                float4 u2 = *(float4*)&W1s[(k + 2) * H + c];
                float4 u3 = *(float4*)&W1s[(k + 3) * H + c];
                float4 v0 = *(float4*)&W2s[(k + 0) * H + c];
                float4 v1 = *(float4*)&W2s[(k + 1) * H + c];
                float4 v2 = *(float4*)&W2s[(k + 2) * H + c];
                float4 v3 = *(float4*)&W2s[(k + 3) * H + c];
                #pragma unroll
                for (int r = 0; r < 4; r++) {
                    float4 a = *(float4*)&As[(r0 + r) * H + k];
                    float4 x = *(float4*)&Xs[(r0 + r) * H + k];
                    acc[r][0] += a.x * u0.x + a.y * u1.x + a.z * u2.x + a.w * u3.x
                               + x.x * v0.x + x.y * v1.x + x.z * v2.x + x.w * v3.x;
                    acc[r][1] += a.x * u0.y + a.y * u1.y + a.z * u2.y + a.w * u3.y
                               + x.x * v0.y + x.y * v1.y + x.z * v2.y + x.w * v3.y;
                    acc[r][2] += a.x * u0.z + a.y * u1.z + a.z * u2.z + a.w * u3.z
                               + x.x * v0.z + x.y * v1.z + x.z * v2.z + x.w * v3.z;
                    acc[r][3] += a.x * u0.w + a.y * u1.w + a.z * u2.w + a.w * u3.w
                               + x.x * v0.w + x.y * v1.w + x.z * v2.w + x.w * v3.w;
                }
            }
            #pragma unroll
            for (int r = 0; r < 4; r++) {
                int row = r0 + r;
                if (row < rows) {
                    float v0 = acc[r][0] + bias.x;
                    float v1 = acc[r][1] + bias.y;
                    float v2 = acc[r][2] + bias.z;
                    float v3 = acc[r][3] + bias.w;
                    float s = v0 + v1 + v2 + v3;
                    #pragma unroll
                    for (int o = 16; o; o >>= 1) s += __shfl_xor_sync(FULLMASK, s, o);
                    float mean = s * (1.f / H);
                    float d0 = v0 - mean, d1 = v1 - mean, d2 = v2 - mean, d3 = v3 - mean;
                    float ss = d0 * d0 + d1 * d1 + d2 * d2 + d3 * d3;
                    #pragma unroll
                    for (int o = 16; o; o >>= 1) ss += __shfl_xor_sync(FULLMASK, ss, o);
                    float rstd = rsqrtf(ss * (1.f / H) + LN_EPS);
                    float4 xr = *(float4*)&Xs[row * H + c];
                    float4 o4;
                    o4.x = fmaxf(d0 * rstd * g4.x + b4.x, 0.f) + xr.x;
                    o4.y = fmaxf(d1 * rstd * g4.y + b4.y, 0.f) + xr.y;
                    o4.z = fmaxf(d2 * rstd * g4.z + b4.z, 0.f) + xr.z;
                    o4.w = fmaxf(d3 * rstd * g4.w + b4.w, 0.f) + xr.w;
                    *(float4*)&g_x[(size_t)(row0 + row) * H + c] = o4;
                }
            }
        }
    }
}

// ---------------- P = x @ Wd1[0:H], Q = x @ Wd1[H:2H] ----------------
__global__ __launch_bounds__(512) void pq_kernel(const float* __restrict__ Wd1, int n) {
    extern __shared__ float sm[];
    float* W1s = sm;
    float* W2s = sm + H * H;
    float* Xs  = sm + 2 * H * H;   // 64*H
    int tid = threadIdx.x;
    for (int i = tid; i < H * H / 4; i += 512) {
        ((float4*)W1s)[i] = ((const float4*)Wd1)[i];
        ((float4*)W2s)[i] = ((const float4*)(Wd1 + H * H))[i];
    }
    int warp = tid >> 5, lane = tid & 31, c = lane * 4;
    __syncthreads();
    for (int tile = blockIdx.x; tile * 64 < n; tile += gridDim.x) {
        int row0 = tile * 64;
        int rows = min(64, n - row0);
        __syncthreads();
        for (int i = tid; i < rows * (H / 4); i += 512)
            ((float4*)Xs)[i] = ((const float4*)(g_x + (size_t)row0 * H))[i];
        __syncthreads();
        int r0 = warp * 4;
        if (r0 < rows) {
            float ap[4][4] = {};
            float aq[4][4] = {};
            for (int k = 0; k < H; k += 4) {
                float4 u0 = *(float4*)&W1s[(k + 0) * H + c];
                float4 u1 = *(float4*)&W1s[(k + 1) * H + c];
                float4 u2 = *(float4*)&W1s[(k + 2) * H + c];
                float4 u3 = *(float4*)&W1s[(k + 3) * H + c];
                float4 v0 = *(float4*)&W2s[(k + 0) * H + c];
                float4 v1 = *(float4*)&W2s[(k + 1) * H + c];
                float4 v2 = *(float4*)&W2s[(k + 2) * H + c];
                float4 v3 = *(float4*)&W2s[(k + 3) * H + c];
                #pragma unroll
                for (int r = 0; r < 4; r++) {
                    float4 a = *(float4*)&Xs[(r0 + r) * H + k];
                    ap[r][0] += a.x * u0.x + a.y * u1.x + a.z * u2.x + a.w * u3.x;
                    ap[r][1] += a.x * u0.y + a.y * u1.y + a.z * u2.y + a.w * u3.y;
                    ap[r][2] += a.x * u0.z + a.y * u1.z + a.z * u2.z + a.w * u3.z;
                    ap[r][3] += a.x * u0.w + a.y * u1.w + a.z * u2.w + a.w * u3.w;
                    aq[r][0] += a.x * v0.x + a.y * v1.x + a.z * v2.x + a.w * v3.x;
                    aq[r][1] += a.x * v0.y + a.y * v1.y + a.z * v2.y + a.w * v3.y;
                    aq[r][2] += a.x * v0.z + a.y * v1.z + a.z * v2.z + a.w * v3.z;
                    aq[r][3] += a.x * v0.w + a.y * v1.w + a.z * v2.w + a.w * v3.w;
                }
            }
            #pragma unroll
            for (int r = 0; r < 4; r++) {
                int row = r0 + r;
                if (row < rows) {
                    size_t off = (size_t)(row0 + row) * H + c;
                    float4 p = {ap[r][0], ap[r][1], ap[r][2], ap[r][3]};
                    float4 q = {aq[r][0], aq[r][1], aq[r][2], aq[r][3]};
                    *(float4*)&g_P[off] = p;
                    *(float4*)&g_Q[off] = q;
                }
            }
        }
    }
}

// ---------------- out[e] = relu(P[src]+Q[dst]+A@Wd1_tail+bd1) @ Wd2 + bd2 ----------------
__global__ __launch_bounds__(256) void decoder_kernel(const int* __restrict__ src,
                                                      const int* __restrict__ dst,
                                                      const float* __restrict__ af,
                                                      const float* __restrict__ Wd1,
                                                      const float* __restrict__ bd1,
                                                      const float* __restrict__ Wd2,
                                                      const float* __restrict__ bd2,
                                                      float* __restrict__ out, int E) {
    __shared__ float Wt[8 * H];
    __shared__ float b1s[H];
    __shared__ float w2s[H];
    int tid = threadIdx.x;
    const float* Wtail = Wd1 + 2 * H * H;
    for (int i = tid; i < 8 * H; i += 256) Wt[i] = Wtail[i];
    if (tid < H) { b1s[tid] = bd1[tid]; w2s[tid] = Wd2[tid]; }
    __syncthreads();
    int lane = tid & 31, c = lane * 4;
    int warp = (blockIdx.x * 256 + tid) >> 5;
    int nwarp = (gridDim.x * 256) >> 5;
    float b2 = __ldg(bd2);
    for (int e = warp; e < E; e += nwarp) {
        int s = __ldg(&src[e]), d = __ldg(&dst[e]);
        float4 p = __ldg((const float4*)&g_P[(size_t)s * H + c]);
        float4 q = __ldg((const float4*)&g_Q[(size_t)d * H + c]);
        const float4* ae = (const float4*)(af + (size_t)e * 8);
        float4 a0 = __ldg(ae), a1 = __ldg(ae + 1);
        float4 b1 = *(float4*)&b1s[c];
        float h0 = p.x + q.x + b1.x, h1 = p.y + q.y + b1.y;
        float h2 = p.z + q.z + b1.z, h3 = p.w + q.w + b1.w;
        float4 w;
        #define DEC_STEP(F, AV) \
            w = *(float4*)&Wt[(F) * H + c]; \
            h0 += (AV) * w.x; h1 += (AV) * w.y; h2 += (AV) * w.z; h3 += (AV) * w.w;
        DEC_STEP(0, a0.x) DEC_STEP(1, a0.y) DEC_STEP(2, a0.z) DEC_STEP(3, a0.w)
        DEC_STEP(4, a1.x) DEC_STEP(5, a1.y) DEC_STEP(6, a1.z) DEC_STEP(7, a1.w)
        #undef DEC_STEP
        h0 = fmaxf(h0, 0.f); h1 = fmaxf(h1, 0.f); h2 = fmaxf(h2, 0.f); h3 = fmaxf(h3, 0.f);
        float4 w2 = *(float4*)&w2s[c];
        float part = h0 * w2.x + h1 * w2.y + h2 * w2.z + h3 * w2.w;
        #pragma unroll
        for (int o = 16; o; o >>= 1) part += __shfl_xor_sync(FULLMASK, part, o);
        if (lane == 0) out[e] = part + b2;
    }
}

// ---------------- launch ----------------
extern "C" void kernel_launch(void* const* d_in, const int* in_sizes, int n_in,
                              void* d_out, int out_size) {
    const int*   ei   = (const int*)d_in[0];
    const float* af   = (const float*)d_in[1];
    const float* hold = (const float*)d_in[2];
    int E = in_sizes[0] / 2;
    int n = in_sizes[2] / H;
    if (E > MAXE) E = MAXE;
    if (n > MAXN) n = MAXN;

    int pi = (n_in >= 19) ? 4 : 3;  // skip num_nodes scalar if present
    const float* Wf    = (const float*)d_in[pi + 0];
    const float* bf    = (const float*)d_in[pi + 1];
    const float* We1   = (const float*)d_in[pi + 2];
    const float* be1   = (const float*)d_in[pi + 3];
    const float* We2   = (const float*)d_in[pi + 4];
    const float* be2   = (const float*)d_in[pi + 5];
    const float* Wrel  = (const float*)d_in[pi + 6];
    const float* brel  = (const float*)d_in[pi + 7];
    const float* Wroot = (const float*)d_in[pi + 8];
    const float* gamma = (const float*)d_in[pi + 9];
    const float* beta  = (const float*)d_in[pi + 10];
    const float* Wd1   = (const float*)d_in[pi + 11];
    const float* bd1   = (const float*)d_in[pi + 12];
    const float* Wd2   = (const float*)d_in[pi + 13];
    const float* bd2   = (const float*)d_in[pi + 14];

    const int* src = ei;
    const int* dst = ei + E;

    size_t smem_xinit = (size_t)(H * H + 64 * H) * sizeof(float);          // 96 KB
    size_t smem_layer = (size_t)(2 * H * H + 2 * 64 * H) * sizeof(float);  // 192 KB
    size_t smem_pq    = (size_t)(2 * H * H + 64 * H) * sizeof(float);      // 160 KB
    cudaFuncSetAttribute(xinit_kernel, cudaFuncAttributeMaxDynamicSharedMemorySize, (int)smem_xinit);
    cudaFuncSetAttribute(layer_kernel, cudaFuncAttributeMaxDynamicSharedMemorySize, (int)smem_layer);
    cudaFuncSetAttribute(pq_kernel, cudaFuncAttributeMaxDynamicSharedMemorySize, (int)smem_pq);

    void *degp = nullptr, *curp = nullptr;
    cudaGetSymbolAddress(&degp, g_deg);
    cudaGetSymbolAddress(&curp, g_cursor);
    cudaMemsetAsync(degp, 0, (size_t)n * sizeof(int), 0);
    cudaMemsetAsync(curp, 0, (size_t)n * sizeof(int), 0);

    c0_kernel<<<1, H>>>(Wf, bf);
    xinit_kernel<<<148, 512, smem_xinit>>>(hold, Wf, n);
    ew_kernel<<<2048, 256>>>(af, We1, be1, We2, be2, E);

    // CSR build (by dst), payload = (src, ew)
    hist_kernel<<<1024, 256>>>(dst, E);
    int nb = (n + 511) / 512;
    scan1_kernel<<<nb, 512>>>(n);
    scan2_kernel<<<1, 256>>>(nb);
    scan3_kernel<<<256, 256>>>(n);
    fill_kernel<<<1024, 256>>>(src, dst, E);

    for (int l = 0; l < 3; l++) {
        gather_kernel<<<6250, 256>>>(n);
        layer_kernel<<<148, 512, smem_layer>>>(Wrel + (size_t)l * H * H, brel + (size_t)l * H,
                                               Wroot + (size_t)l * H * H, gamma + (size_t)l * H,
                                               beta + (size_t)l * H, n);
    }

    pq_kernel<<<148, 512, smem_pq>>>(Wd1, n);
    decoder_kernel<<<2048, 256>>>(src, dst, af, Wd1, bd1, Wd2, bd2, (float*)d_out, E);
}

// round 3
// speedup vs baseline: 1.0168x; 1.0038x over previous
#include <cuda_runtime.h>

#define H 128
#define MAXN 50000
#define MAXE 800000
#define LN_EPS 1e-5f
#define FULLMASK 0xffffffffu

// ---------------- device scratch (no allocations allowed) ----------------
__device__ float g_x[(size_t)MAXN * H];
__device__ float g_agg[(size_t)MAXN * H];
__device__ float g_P[(size_t)MAXN * H];
__device__ float g_Q[(size_t)MAXN * H];
__device__ float g_ew[MAXE];
__device__ int   g_srcs[MAXE];   // dst-sorted src ids   (payload CSR)
__device__ float g_ews[MAXE];    // dst-sorted edge weights
__device__ int   g_rowptr[MAXN + 1];
__device__ int   g_deg[MAXN];
__device__ int   g_cursor[MAXN];
__device__ int   g_part[256];
__device__ float g_c0[H];

// ---------------- c0 = colsum(Wf[:H]) + bf ----------------
__global__ void c0_kernel(const float* __restrict__ Wf, const float* __restrict__ bf) {
    int j = threadIdx.x;
    float s = bf[j];
    #pragma unroll 8
    for (int i = 0; i < H; i++) s += Wf[i * H + j];
    g_c0[j] = s;
}

// ---------------- x = relu(h_old @ Wf[H:2H] + c0) ----------------
__global__ __launch_bounds__(512) void xinit_kernel(const float* __restrict__ hold,
                                                    const float* __restrict__ Wf, int n) {
    extern __shared__ float sm[];
    float* Ws = sm;            // H*H floats
    float* As = sm + H * H;    // 64*H floats
    const float4* W2 = (const float4*)(Wf + H * H);
    int tid = threadIdx.x;
    for (int i = tid; i < H * H / 4; i += 512) ((float4*)Ws)[i] = W2[i];
    int warp = tid >> 5, lane = tid & 31, c = lane * 4;
    __syncthreads();
    float4 bias = *(const float4*)&g_c0[c];

    for (int tile = blockIdx.x; tile * 64 < n; tile += gridDim.x) {
        int row0 = tile * 64;
        int rows = min(64, n - row0);
        __syncthreads();
        for (int i = tid; i < rows * (H / 4); i += 512)
            ((float4*)As)[i] = ((const float4*)(hold + (size_t)row0 * H))[i];
        __syncthreads();
        int r0 = warp * 4;
        if (r0 < rows) {
            float acc[4][4] = {};
            #pragma unroll 4
            for (int k = 0; k < H; k += 4) {
                float4 w0 = *(float4*)&Ws[(k + 0) * H + c];
                float4 w1 = *(float4*)&Ws[(k + 1) * H + c];
                float4 w2 = *(float4*)&Ws[(k + 2) * H + c];
                float4 w3 = *(float4*)&Ws[(k + 3) * H + c];
                #pragma unroll
                for (int r = 0; r < 4; r++) {
                    float4 a = *(float4*)&As[(r0 + r) * H + k];
                    acc[r][0] += a.x * w0.x + a.y * w1.x + a.z * w2.x + a.w * w3.x;
                    acc[r][1] += a.x * w0.y + a.y * w1.y + a.z * w2.y + a.w * w3.y;
                    acc[r][2] += a.x * w0.z + a.y * w1.z + a.z * w2.z + a.w * w3.z;
                    acc[r][3] += a.x * w0.w + a.y * w1.w + a.z * w2.w + a.w * w3.w;
                }
            }
            #pragma unroll
            for (int r = 0; r < 4; r++) {
                if (r0 + r < rows) {
                    float4 o;
                    o.x = fmaxf(acc[r][0] + bias.x, 0.f);
                    o.y = fmaxf(acc[r][1] + bias.y, 0.f);
                    o.z = fmaxf(acc[r][2] + bias.z, 0.f);
                    o.w = fmaxf(acc[r][3] + bias.w, 0.f);
                    *(float4*)&g_x[(size_t)(row0 + r0 + r) * H + c] = o;
                }
            }
        }
    }
}

// ---------------- ew = sigmoid(relu(A @ We1 + be1) @ We2 + be2) ----------------
__global__ __launch_bounds__(256) void ew_kernel(const float* __restrict__ af,
                                                 const float* __restrict__ We1,
                                                 const float* __restrict__ be1,
                                                 const float* __restrict__ We2,
                                                 const float* __restrict__ be2, int E) {
    __shared__ float W1s[8 * H];
    __shared__ float b1s[H];
    __shared__ float w2s[H];
    int tid = threadIdx.x;
    for (int i = tid; i < 8 * H; i += 256) W1s[i] = We1[i];
    if (tid < H) { b1s[tid] = be1[tid]; w2s[tid] = We2[tid]; }
    __syncthreads();
    int lane = tid & 31, c = lane * 4;
    int warp = (blockIdx.x * 256 + tid) >> 5;
    int nwarp = (gridDim.x * 256) >> 5;
    float b2 = __ldg(be2);
    for (int e = warp; e < E; e += nwarp) {
        const float4* ae = (const float4*)(af + (size_t)e * 8);
        float4 a0 = __ldg(ae), a1 = __ldg(ae + 1);
        float4 acc = *(float4*)&b1s[c];
        float4 w;
        #define EW_STEP(F, AV) \
            w = *(float4*)&W1s[(F) * H + c]; \
            acc.x += (AV) * w.x; acc.y += (AV) * w.y; acc.z += (AV) * w.z; acc.w += (AV) * w.w;
        EW_STEP(0, a0.x) EW_STEP(1, a0.y) EW_STEP(2, a0.z) EW_STEP(3, a0.w)
        EW_STEP(4, a1.x) EW_STEP(5, a1.y) EW_STEP(6, a1.z) EW_STEP(7, a1.w)
        #undef EW_STEP
        acc.x = fmaxf(acc.x, 0.f); acc.y = fmaxf(acc.y, 0.f);
        acc.z = fmaxf(acc.z, 0.f); acc.w = fmaxf(acc.w, 0.f);
        float4 w2 = *(float4*)&w2s[c];
        float p = acc.x * w2.x + acc.y * w2.y + acc.z * w2.z + acc.w * w2.w;
        #pragma unroll
        for (int o = 16; o; o >>= 1) p += __shfl_xor_sync(FULLMASK, p, o);
        if (lane == 0) g_ew[e] = 1.f / (1.f + __expf(-(p + b2)));
    }
}

// ---------------- CSR build ----------------
__global__ void hist_kernel(const int* __restrict__ dst, int E) {
    for (int i = blockIdx.x * blockDim.x + threadIdx.x; i < E; i += gridDim.x * blockDim.x)
        atomicAdd(&g_deg[dst[i]], 1);
}

__global__ void scan1_kernel(int n) {
    __shared__ int s[512];
    int i = blockIdx.x * 512 + threadIdx.x;
    int v = (i < n) ? g_deg[i] : 0;
    s[threadIdx.x] = v;
    __syncthreads();
    for (int off = 1; off < 512; off <<= 1) {
        int t = (threadIdx.x >= off) ? s[threadIdx.x - off] : 0;
        __syncthreads();
        s[threadIdx.x] += t;
        __syncthreads();
    }
    if (i < n) g_rowptr[i + 1] = s[threadIdx.x];
    if (threadIdx.x == 511) g_part[blockIdx.x] = s[511];
    if (i == 0) g_rowptr[0] = 0;
}

__global__ void scan2_kernel(int nb) {
    __shared__ int s[256];
    int v = (threadIdx.x < nb) ? g_part[threadIdx.x] : 0;
    s[threadIdx.x] = v;
    __syncthreads();
    for (int off = 1; off < 256; off <<= 1) {
        int t = (threadIdx.x >= off) ? s[threadIdx.x - off] : 0;
        __syncthreads();
        s[threadIdx.x] += t;
        __syncthreads();
    }
    if (threadIdx.x < nb) g_part[threadIdx.x] = s[threadIdx.x] - v;  // exclusive
}

__global__ void scan3_kernel(int n) {
    for (int i = blockIdx.x * blockDim.x + threadIdx.x; i < n; i += gridDim.x * blockDim.x)
        g_rowptr[i + 1] += g_part[i >> 9];
}

// fill: scatter (src, ew) payload into dst-sorted CSR order
__global__ void fill_kernel(const int* __restrict__ src, const int* __restrict__ dst, int E) {
    for (int i = blockIdx.x * blockDim.x + threadIdx.x; i < E; i += gridDim.x * blockDim.x) {
        int d = dst[i];
        int p = atomicAdd(&g_cursor[d], 1);
        int pos = g_rowptr[d] + p;
        g_srcs[pos] = src[i];
        g_ews[pos]  = g_ew[i];
    }
}

// ---------------- agg[i] = sum_{e: dst=i} ew[e] * x[src[e]] (atomic-free, MLP=4) ----------------
__global__ __launch_bounds__(256) void gather_kernel(int n) {
    int lane = threadIdx.x & 31, c = lane * 4;
    int warp = (blockIdx.x * 256 + threadIdx.x) >> 5;
    int nwarp = (gridDim.x * 256) >> 5;
    for (int node = warp; node < n; node += nwarp) {
        int b = __ldg(&g_rowptr[node]), e = __ldg(&g_rowptr[node + 1]);
        float4 acc = {0.f, 0.f, 0.f, 0.f};
        int t = b;
        for (; t + 4 <= e; t += 4) {
            // batch the metadata loads (contiguous, uniform) then 4 independent row loads
            int s0 = __ldg(&g_srcs[t + 0]), s1 = __ldg(&g_srcs[t + 1]);
            int s2 = __ldg(&g_srcs[t + 2]), s3 = __ldg(&g_srcs[t + 3]);
            float w0 = __ldg(&g_ews[t + 0]), w1 = __ldg(&g_ews[t + 1]);
            float w2 = __ldg(&g_ews[t + 2]), w3 = __ldg(&g_ews[t + 3]);
            float4 v0 = __ldg((const float4*)&g_x[(size_t)s0 * H + c]);
            float4 v1 = __ldg((const float4*)&g_x[(size_t)s1 * H + c]);
            float4 v2 = __ldg((const float4*)&g_x[(size_t)s2 * H + c]);
            float4 v3 = __ldg((const float4*)&g_x[(size_t)s3 * H + c]);
            acc.x += w0 * v0.x; acc.y += w0 * v0.y; acc.z += w0 * v0.z; acc.w += w0 * v0.w;
            acc.x += w1 * v1.x; acc.y += w1 * v1.y; acc.z += w1 * v1.z; acc.w += w1 * v1.w;
            acc.x += w2 * v2.x; acc.y += w2 * v2.y; acc.z += w2 * v2.z; acc.w += w2 * v2.w;
            acc.x += w3 * v3.x; acc.y += w3 * v3.y; acc.z += w3 * v3.z; acc.w += w3 * v3.w;
        }
        for (; t < e; t++) {
            int s = __ldg(&g_srcs[t]);
            float w = __ldg(&g_ews[t]);
            float4 v = __ldg((const float4*)&g_x[(size_t)s * H + c]);
            acc.x += w * v.x; acc.y += w * v.y; acc.z += w * v.z; acc.w += w * v.w;
        }
        *(float4*)&g_agg[(size_t)node * H + c] = acc;
    }
}

// ---------------- x = relu(LN(agg@Wrel + brel + x@Wroot)) + x ----------------
__global__ __launch_bounds__(512) void layer_kernel(const float* __restrict__ Wrel,
                                                    const float* __restrict__ brel,
                                                    const float* __restrict__ Wroot,
                                                    const float* __restrict__ gamma,
                                                    const float* __restrict__ beta, int n) {
    extern __shared__ float sm[];
    float* W1s = sm;                 // H*H
    float* W2s = sm + H * H;         // H*H
    float* As  = sm + 2 * H * H;     // 64*H (agg tile)
    float* Xs  = sm + 2 * H * H + 64 * H;  // 64*H (x tile)
    int tid = threadIdx.x;
    for (int i = tid; i < H * H / 4; i += 512) {
        ((float4*)W1s)[i] = ((const float4*)Wrel)[i];
        ((float4*)W2s)[i] = ((const float4*)Wroot)[i];
    }
    int warp = tid >> 5, lane = tid & 31, c = lane * 4;
    __syncthreads();
    float4 bias = *(const float4*)&brel[c];
    float4 g4   = *(const float4*)&gamma[c];
    float4 b4   = *(const float4*)&beta[c];

    for (int tile = blockIdx.x; tile * 64 < n; tile += gridDim.x) {
        int row0 = tile * 64;
        int rows = min(64, n - row0);
        __syncthreads();
        for (int i = tid; i < rows * (H / 4); i += 512) {
            ((float4*)As)[i] = ((const float4*)(g_agg + (size_t)row0 * H))[i];
            ((float4*)Xs)[i] = ((const float4*)(g_x + (size_t)row0 * H))[i];
        }
        __syncthreads();
        int r0 = warp * 4;
        if (r0 < rows) {
            float acc[4][4] = {};
            #pragma unroll 2
            for (int k = 0; k < H; k += 4) {
                float4 u0 = *(float4*)&W1s[(k + 0) * H + c];
                float4 u1 = *(float4*)&W1s[(k + 1) * H + c];
                float4 u2 = *(float4*)&W1s[(k + 2) * H + c];
                float4 u3 = *(float4*)&W1s[(k + 3) * H + c];
                float4 v0 = *(float4*)&W2s[(k + 0) * H + c];
                float4 v1 = *(float4*)&W2s[(k + 1) * H + c];
                float4 v2 = *(float4*)&W2s[(k + 2) * H + c];
                float4 v3 = *(float4*)&W2s[(k + 3) * H + c];
                #pragma unroll
                for (int r = 0; r < 4; r++) {
                    float4 a = *(float4*)&As[(r0 + r) * H + k];
                    float4 x = *(float4*)&Xs[(r0 + r) * H + k];
                    acc[r][0] += a.x * u0.x + a.y * u1.x + a.z * u2.x + a.w * u3.x
                               + x.x * v0.x + x.y * v1.x + x.z * v2.x + x.w * v3.x;
                    acc[r][1] += a.x * u0.y + a.y * u1.y + a.z * u2.y + a.w * u3.y
                               + x.x * v0.y + x.y * v1.y + x.z * v2.y + x.w * v3.y;
                    acc[r][2] += a.x * u0.z + a.y * u1.z + a.z * u2.z + a.w * u3.z
                               + x.x * v0.z + x.y * v1.z + x.z * v2.z + x.w * v3.z;
                    acc[r][3] += a.x * u0.w + a.y * u1.w + a.z * u2.w + a.w * u3.w
                               + x.x * v0.w + x.y * v1.w + x.z * v2.w + x.w * v3.w;
                }
            }
            #pragma unroll
            for (int r = 0; r < 4; r++) {
                int row = r0 + r;
                if (row < rows) {
                    float v0 = acc[r][0] + bias.x;
                    float v1 = acc[r][1] + bias.y;
                    float v2 = acc[r][2] + bias.z;
                    float v3 = acc[r][3] + bias.w;
                    float s = v0 + v1 + v2 + v3;
                    #pragma unroll
                    for (int o = 16; o; o >>= 1) s += __shfl_xor_sync(FULLMASK, s, o);
                    float mean = s * (1.f / H);
                    float d0 = v0 - mean, d1 = v1 - mean, d2 = v2 - mean, d3 = v3 - mean;
                    float ss = d0 * d0 + d1 * d1 + d2 * d2 + d3 * d3;
                    #pragma unroll
                    for (int o = 16; o; o >>= 1) ss += __shfl_xor_sync(FULLMASK, ss, o);
                    float rstd = rsqrtf(ss * (1.f / H) + LN_EPS);
                    float4 xr = *(float4*)&Xs[row * H + c];
                    float4 o4;
                    o4.x = fmaxf(d0 * rstd * g4.x + b4.x, 0.f) + xr.x;
                    o4.y = fmaxf(d1 * rstd * g4.y + b4.y, 0.f) + xr.y;
                    o4.z = fmaxf(d2 * rstd * g4.z + b4.z, 0.f) + xr.z;
                    o4.w = fmaxf(d3 * rstd * g4.w + b4.w, 0.f) + xr.w;
                    *(float4*)&g_x[(size_t)(row0 + row) * H + c] = o4;
                }
            }
        }
    }
}

// ---------------- P = x @ Wd1[0:H], Q = x @ Wd1[H:2H] ----------------
__global__ __launch_bounds__(512) void pq_kernel(const float* __restrict__ Wd1, int n) {
    extern __shared__ float sm[];
    float* W1s = sm;
    float* W2s = sm + H * H;
    float* Xs  = sm + 2 * H * H;   // 64*H
    int tid = threadIdx.x;
    for (int i = tid; i < H * H / 4; i += 512) {
        ((float4*)W1s)[i] = ((const float4*)Wd1)[i];
        ((float4*)W2s)[i] = ((const float4*)(Wd1 + H * H))[i];
    }
    int warp = tid >> 5, lane = tid & 31, c = lane * 4;
    __syncthreads();
    for (int tile = blockIdx.x; tile * 64 < n; tile += gridDim.x) {
        int row0 = tile * 64;
        int rows = min(64, n - row0);
        __syncthreads();
        for (int i = tid; i < rows * (H / 4); i += 512)
            ((float4*)Xs)[i] = ((const float4*)(g_x + (size_t)row0 * H))[i];
        __syncthreads();
        int r0 = warp * 4;
        if (r0 < rows) {
            float ap[4][4] = {};
            float aq[4][4] = {};
            for (int k = 0; k < H; k += 4) {
                float4 u0 = *(float4*)&W1s[(k + 0) * H + c];
                float4 u1 = *(float4*)&W1s[(k + 1) * H + c];
                float4 u2 = *(float4*)&W1s[(k + 2) * H + c];
                float4 u3 = *(float4*)&W1s[(k + 3) * H + c];
                float4 v0 = *(float4*)&W2s[(k + 0) * H + c];
                float4 v1 = *(float4*)&W2s[(k + 1) * H + c];
                float4 v2 = *(float4*)&W2s[(k + 2) * H + c];
                float4 v3 = *(float4*)&W2s[(k + 3) * H + c];
                #pragma unroll
                for (int r = 0; r < 4; r++) {
                    float4 a = *(float4*)&Xs[(r0 + r) * H + k];
                    ap[r][0] += a.x * u0.x + a.y * u1.x + a.z * u2.x + a.w * u3.x;
                    ap[r][1] += a.x * u0.y + a.y * u1.y + a.z * u2.y + a.w * u3.y;
                    ap[r][2] += a.x * u0.z + a.y * u1.z + a.z * u2.z + a.w * u3.z;
                    ap[r][3] += a.x * u0.w + a.y * u1.w + a.z * u2.w + a.w * u3.w;
                    aq[r][0] += a.x * v0.x + a.y * v1.x + a.z * v2.x + a.w * v3.x;
                    aq[r][1] += a.x * v0.y + a.y * v1.y + a.z * v2.y + a.w * v3.y;
                    aq[r][2] += a.x * v0.z + a.y * v1.z + a.z * v2.z + a.w * v3.z;
                    aq[r][3] += a.x * v0.w + a.y * v1.w + a.z * v2.w + a.w * v3.w;
                }
            }
            #pragma unroll
            for (int r = 0; r < 4; r++) {
                int row = r0 + r;
                if (row < rows) {
                    size_t off = (size_t)(row0 + row) * H + c;
                    float4 p = {ap[r][0], ap[r][1], ap[r][2], ap[r][3]};
                    float4 q = {aq[r][0], aq[r][1], aq[r][2], aq[r][3]};
                    *(float4*)&g_P[off] = p;
                    *(float4*)&g_Q[off] = q;
                }
            }
        }
    }
}

// ---------------- out[e] = relu(P[src]+Q[dst]+A@Wd1_tail+bd1) @ Wd2 + bd2 ----------------
__global__ __launch_bounds__(256) void decoder_kernel(const int* __restrict__ src,
                                                      const int* __restrict__ dst,
                                                      const float* __restrict__ af,
                                                      const float* __restrict__ Wd1,
                                                      const float* __restrict__ bd1,
                                                      const float* __restrict__ Wd2,
                                                      const float* __restrict__ bd2,
                                                      float* __restrict__ out, int E) {
    __shared__ float Wt[8 * H];
    __shared__ float b1s[H];
    __shared__ float w2s[H];
    int tid = threadIdx.x;
    const float* Wtail = Wd1 + 2 * H * H;
    for (int i = tid; i < 8 * H; i += 256) Wt[i] = Wtail[i];
    if (tid < H) { b1s[tid] = bd1[tid]; w2s[tid] = Wd2[tid]; }
    __syncthreads();
    int lane = tid & 31, c = lane * 4;
    int warp = (blockIdx.x * 256 + tid) >> 5;
    int nwarp = (gridDim.x * 256) >> 5;
    float b2 = __ldg(bd2);
    for (int e = warp; e < E; e += nwarp) {
        int s = __ldg(&src[e]), d = __ldg(&dst[e]);
        float4 p = __ldg((const float4*)&g_P[(size_t)s * H + c]);
        float4 q = __ldg((const float4*)&g_Q[(size_t)d * H + c]);
        const float4* ae = (const float4*)(af + (size_t)e * 8);
        float4 a0 = __ldg(ae), a1 = __ldg(ae + 1);
        float4 b1 = *(float4*)&b1s[c];
        float h0 = p.x + q.x + b1.x, h1 = p.y + q.y + b1.y;
        float h2 = p.z + q.z + b1.z, h3 = p.w + q.w + b1.w;
        float4 w;
        #define DEC_STEP(F, AV) \
            w = *(float4*)&Wt[(F) * H + c]; \
            h0 += (AV) * w.x; h1 += (AV) * w.y; h2 += (AV) * w.z; h3 += (AV) * w.w;
        DEC_STEP(0, a0.x) DEC_STEP(1, a0.y) DEC_STEP(2, a0.z) DEC_STEP(3, a0.w)
        DEC_STEP(4, a1.x) DEC_STEP(5, a1.y) DEC_STEP(6, a1.z) DEC_STEP(7, a1.w)
        #undef DEC_STEP
        h0 = fmaxf(h0, 0.f); h1 = fmaxf(h1, 0.f); h2 = fmaxf(h2, 0.f); h3 = fmaxf(h3, 0.f);
        float4 w2 = *(float4*)&w2s[c];
        float part = h0 * w2.x + h1 * w2.y + h2 * w2.z + h3 * w2.w;
        #pragma unroll
        for (int o = 16; o; o >>= 1) part += __shfl_xor_sync(FULLMASK, part, o);
        if (lane == 0) out[e] = part + b2;
    }
}

// ---------------- launch ----------------
extern "C" void kernel_launch(void* const* d_in, const int* in_sizes, int n_in,
                              void* d_out, int out_size) {
    const int*   ei   = (const int*)d_in[0];
    const float* af   = (const float*)d_in[1];
    const float* hold = (const float*)d_in[2];
    int E = in_sizes[0] / 2;
    int n = in_sizes[2] / H;
    if (E > MAXE) E = MAXE;
    if (n > MAXN) n = MAXN;

    int pi = (n_in >= 19) ? 4 : 3;  // skip num_nodes scalar if present
    const float* Wf    = (const float*)d_in[pi + 0];
    const float* bf    = (const float*)d_in[pi + 1];
    const float* We1   = (const float*)d_in[pi + 2];
    const float* be1   = (const float*)d_in[pi + 3];
    const float* We2   = (const float*)d_in[pi + 4];
    const float* be2   = (const float*)d_in[pi + 5];
    const float* Wrel  = (const float*)d_in[pi + 6];
    const float* brel  = (const float*)d_in[pi + 7];
    const float* Wroot = (const float*)d_in[pi + 8];
    const float* gamma = (const float*)d_in[pi + 9];
    const float* beta  = (const float*)d_in[pi + 10];
    const float* Wd1   = (const float*)d_in[pi + 11];
    const float* bd1   = (const float*)d_in[pi + 12];
    const float* Wd2   = (const float*)d_in[pi + 13];
    const float* bd2   = (const float*)d_in[pi + 14];

    const int* src = ei;
    const int* dst = ei + E;

    size_t smem_xinit = (size_t)(H * H + 64 * H) * sizeof(float);          // 96 KB
    size_t smem_layer = (size_t)(2 * H * H + 2 * 64 * H) * sizeof(float);  // 192 KB
    size_t smem_pq    = (size_t)(2 * H * H + 64 * H) * sizeof(float);      // 160 KB
    cudaFuncSetAttribute(xinit_kernel, cudaFuncAttributeMaxDynamicSharedMemorySize, (int)smem_xinit);
    cudaFuncSetAttribute(layer_kernel, cudaFuncAttributeMaxDynamicSharedMemorySize, (int)smem_layer);
    cudaFuncSetAttribute(pq_kernel, cudaFuncAttributeMaxDynamicSharedMemorySize, (int)smem_pq);

    void *degp = nullptr, *curp = nullptr;
    cudaGetSymbolAddress(&degp, g_deg);
    cudaGetSymbolAddress(&curp, g_cursor);
    cudaMemsetAsync(degp, 0, (size_t)n * sizeof(int), 0);
    cudaMemsetAsync(curp, 0, (size_t)n * sizeof(int), 0);

    c0_kernel<<<1, H>>>(Wf, bf);
    xinit_kernel<<<148, 512, smem_xinit>>>(hold, Wf, n);
    ew_kernel<<<2048, 256>>>(af, We1, be1, We2, be2, E);

    // CSR build (by dst), payload = (src, ew)
    hist_kernel<<<1024, 256>>>(dst, E);
    int nb = (n + 511) / 512;
    scan1_kernel<<<nb, 512>>>(n);
    scan2_kernel<<<1, 256>>>(nb);
    scan3_kernel<<<256, 256>>>(n);
    fill_kernel<<<1024, 256>>>(src, dst, E);

    for (int l = 0; l < 3; l++) {
        gather_kernel<<<6250, 256>>>(n);
        layer_kernel<<<148, 512, smem_layer>>>(Wrel + (size_t)l * H * H, brel + (size_t)l * H,
                                               Wroot + (size_t)l * H * H, gamma + (size_t)l * H,
                                               beta + (size_t)l * H, n);
    }

    pq_kernel<<<148, 512, smem_pq>>>(Wd1, n);
    decoder_kernel<<<2048, 256>>>(src, dst, af, Wd1, bd1, Wd2, bd2, (float*)d_out, E);
}

// round 5
// speedup vs baseline: 1.1524x; 1.1333x over previous
#include <cuda_runtime.h>
#include <cuda_bf16.h>
#include <cstdint>

#define H 128
#define MAXN 50000
#define MAXE 800000
#define LN_EPS 1e-5f
#define FULLMASK 0xffffffffu
typedef __nv_bfloat16 bf16;

// tile geometry: 128x128 out tile, smem rows padded to 136 bf16 (272B) for
// conflict-free fragment loads; epilogue fp32 buffer stride 132 floats.
#define TBE (128 * 136)                    // bf16 elems per tile buffer
#define MM_SMEM (5 * TBE * 2)              // 174080 bytes (mode1 worst case)

// ---------------- device scratch ----------------
__device__ float g_x[(size_t)MAXN * H];
__device__ float g_agg[(size_t)MAXN * H];
__device__ float g_P[(size_t)MAXN * H];
__device__ float g_Q[(size_t)MAXN * H];
__device__ float g_ew[MAXE];
__device__ int   g_srcs[MAXE];
__device__ float g_ews[MAXE];
__device__ int   g_rowptr[MAXN + 1];
__device__ int   g_deg[MAXN];
__device__ int   g_cursor[MAXN];
__device__ int   g_part[256];
__device__ float g_c0[H];
__device__ __align__(16) bf16 g_wbh[9 * H * H];
__device__ __align__(16) bf16 g_wbl[9 * H * H];

// ---------------- warp MMA ----------------
__device__ __forceinline__ void mma16816(float* d, const uint32_t* a, const uint32_t* b) {
    asm volatile(
        "mma.sync.aligned.m16n8k16.row.col.f32.bf16.bf16.f32 "
        "{%0,%1,%2,%3}, {%4,%5,%6,%7}, {%8,%9}, {%0,%1,%2,%3};"
        : "+f"(d[0]), "+f"(d[1]), "+f"(d[2]), "+f"(d[3])
        : "r"(a[0]), "r"(a[1]), "r"(a[2]), "r"(a[3]), "r"(b[0]), "r"(b[1]));
}

// one K=128 product pass over a stage's W tile. A2t optional (second A tile
// sharing the same B fragments).
__device__ __forceinline__ void do_stage(float acc[2][8][4], const bf16* A0t, const bf16* A1t,
                                         const bf16* Wt, int warpM, int warpN, int lane) {
    int r = lane >> 2, c2 = (lane & 3) * 2;
    #pragma unroll
    for (int ks = 0; ks < 8; ks++) {
        int k0 = ks * 16;
        uint32_t b[8][2];
        #pragma unroll
        for (int nf = 0; nf < 8; nf++) {
            const bf16* wp = Wt + (size_t)(warpN * 64 + nf * 8 + r) * 136 + k0 + c2;
            b[nf][0] = *(const uint32_t*)wp;
            b[nf][1] = *(const uint32_t*)(wp + 8);
        }
        #pragma unroll
        for (int t = 0; t < 2; t++) {
            const bf16* A = t ? A1t : A0t;
            if (t && A1t == nullptr) break;
            uint32_t a[2][4];
            #pragma unroll
            for (int mf = 0; mf < 2; mf++) {
                const bf16* ap = A + (size_t)(warpM * 32 + mf * 16 + r) * 136 + k0 + c2;
                a[mf][0] = *(const uint32_t*)ap;
                a[mf][1] = *(const uint32_t*)(ap + 8 * 136);
                a[mf][2] = *(const uint32_t*)(ap + 8);
                a[mf][3] = *(const uint32_t*)(ap + 8 * 136 + 8);
            }
            #pragma unroll
            for (int mf = 0; mf < 2; mf++)
                #pragma unroll
                for (int nf = 0; nf < 8; nf++)
                    mma16816(acc[mf][nf], a[mf], b[nf]);
        }
    }
}

__device__ __forceinline__ void cvt_tile(bf16* sh, bf16* sl, const float* src,
                                         int row0, int rows, int tid) {
    for (int i = tid; i < 4096; i += 256) {
        int row = i >> 5, k = (i & 31) * 4;
        float4 v = (row < rows) ? *(const float4*)&src[(size_t)(row0 + row) * H + k]
                                : make_float4(0.f, 0.f, 0.f, 0.f);
        bf16 h0 = __float2bfloat16(v.x), h1 = __float2bfloat16(v.y);
        bf16 h2 = __float2bfloat16(v.z), h3 = __float2bfloat16(v.w);
        __nv_bfloat162 hp0 = {h0, h1}, hp1 = {h2, h3};
        __nv_bfloat162 lp0 = __floats2bfloat162_rn(v.x - __bfloat162float(h0), v.y - __bfloat162float(h1));
        __nv_bfloat162 lp1 = __floats2bfloat162_rn(v.z - __bfloat162float(h2), v.w - __bfloat162float(h3));
        size_t off = (size_t)row * 136 + k;
        *(uint2*)&sh[off] = make_uint2(*(uint32_t*)&hp0, *(uint32_t*)&hp1);
        *(uint2*)&sl[off] = make_uint2(*(uint32_t*)&lp0, *(uint32_t*)&lp1);
    }
}
__device__ __forceinline__ void copy_w(bf16* sW, const bf16* w, int tid) {
    for (int i = tid; i < 2048; i += 256) {
        int nrow = i >> 4, k = (i & 15) * 8;
        *(uint4*)&sW[(size_t)nrow * 136 + k] = *(const uint4*)&w[(size_t)nrow * 128 + k];
    }
}

// mode 0: out = relu(A1@W1 + bias)
// mode 1: out = relu(LN(A1@W1 + A2@W2 + bias; gamma,beta)) + A2
// mode 3: out = A1@W1
__global__ __launch_bounds__(256) void mm_kernel(
    int mode, const float* __restrict__ A1, const float* __restrict__ A2,
    const bf16* __restrict__ w1h, const bf16* __restrict__ w1l,
    const bf16* __restrict__ w2h, const bf16* __restrict__ w2l,
    const float* __restrict__ bias, const float* __restrict__ gamma,
    const float* __restrict__ beta, float* __restrict__ out1, int n) {
    extern __shared__ char sm[];
    bf16* sAh = (bf16*)sm;
    bf16* sAl = sAh + TBE;
    bf16* sXh = sAl + TBE;
    bf16* sXl = sXh + TBE;
    bf16* sW  = sAh + (mode == 1 ? 4 : 2) * TBE;
    float* sD = (float*)sm;

    int tid = threadIdx.x, wid = tid >> 5, lane = tid & 31;
    int warpM = wid >> 1, warpN = wid & 1;
    int row0 = blockIdx.x * 128;
    int rows = min(128, n - row0);

    cvt_tile(sAh, sAl, A1, row0, rows, tid);
    if (mode == 1) cvt_tile(sXh, sXl, A2, row0, rows, tid);
    __syncthreads();

    float acc[2][8][4];
    #pragma unroll
    for (int mf = 0; mf < 2; mf++)
        #pragma unroll
        for (int nf = 0; nf < 8; nf++)
            #pragma unroll
            for (int j = 0; j < 4; j++) acc[mf][nf][j] = 0.f;

    int nst = (mode == 1) ? 4 : 2;
    for (int st = 0; st < nst; st++) {
        const bf16* wsrc = (st == 0) ? w1h : (st == 1) ? w1l : (st == 2) ? w2h : w2l;
        copy_w(sW, wsrc, tid);
        __syncthreads();
        const bf16* A0t = (st < 2) ? sAh : sXh;
        const bf16* A1t = (st == 0) ? sAl : (st == 2) ? sXl : nullptr;
        do_stage(acc, A0t, A1t, sW, warpM, warpN, lane);
        __syncthreads();
    }

    // dump accumulators to smem fp32 buffer (stride 132)
    {
        int r = lane >> 2, c2 = (lane & 3) * 2;
        #pragma unroll
        for (int mf = 0; mf < 2; mf++)
            #pragma unroll
            for (int nf = 0; nf < 8; nf++) {
                int row = warpM * 32 + mf * 16 + r;
                int col = warpN * 64 + nf * 8 + c2;
                *(float2*)&sD[(size_t)row * 132 + col] = make_float2(acc[mf][nf][0], acc[mf][nf][1]);
                *(float2*)&sD[(size_t)(row + 8) * 132 + col] = make_float2(acc[mf][nf][2], acc[mf][nf][3]);
            }
    }
    __syncthreads();

    if (mode == 1) {
        // warp per row, 16 rows per warp; lane holds 4 cols
        for (int rr = 0; rr < 16; rr++) {
            int row = wid * 16 + rr;
            if (row >= rows) break;
            int c = lane * 4;
            float4 v = *(float4*)&sD[(size_t)row * 132 + c];
            v.x += __ldg(&bias[c + 0]); v.y += __ldg(&bias[c + 1]);
            v.z += __ldg(&bias[c + 2]); v.w += __ldg(&bias[c + 3]);
            float s = v.x + v.y + v.z + v.w;
            #pragma unroll
            for (int o = 16; o; o >>= 1) s += __shfl_xor_sync(FULLMASK, s, o);
            float mean = s * (1.f / H);
            float d0 = v.x - mean, d1 = v.y - mean, d2 = v.z - mean, d3 = v.w - mean;
            float ss = d0 * d0 + d1 * d1 + d2 * d2 + d3 * d3;
            #pragma unroll
            for (int o = 16; o; o >>= 1) ss += __shfl_xor_sync(FULLMASK, ss, o);
            float rstd = rsqrtf(ss * (1.f / H) + LN_EPS);
            size_t gro = (size_t)(row0 + row) * H + c;
            float4 xr = *(const float4*)&A2[gro];
            float4 o4;
            o4.x = fmaxf(d0 * rstd * __ldg(&gamma[c + 0]) + __ldg(&beta[c + 0]), 0.f) + xr.x;
            o4.y = fmaxf(d1 * rstd * __ldg(&gamma[c + 1]) + __ldg(&beta[c + 1]), 0.f) + xr.y;
            o4.z = fmaxf(d2 * rstd * __ldg(&gamma[c + 2]) + __ldg(&beta[c + 2]), 0.f) + xr.z;
            o4.w = fmaxf(d3 * rstd * __ldg(&gamma[c + 3]) + __ldg(&beta[c + 3]), 0.f) + xr.w;
            *(float4*)&out1[gro] = o4;
        }
    } else {
        for (int i = tid; i < 4096; i += 256) {
            int row = i >> 5, k = (i & 31) * 4;
            if (row >= rows) continue;
            float4 v = *(float4*)&sD[(size_t)row * 132 + k];
            if (mode == 0) {
                v.x = fmaxf(v.x + __ldg(&bias[k + 0]), 0.f);
                v.y = fmaxf(v.y + __ldg(&bias[k + 1]), 0.f);
                v.z = fmaxf(v.z + __ldg(&bias[k + 2]), 0.f);
                v.w = fmaxf(v.w + __ldg(&bias[k + 3]), 0.f);
            }
            *(float4*)&out1[(size_t)(row0 + row) * H + k] = v;
        }
    }
}

// ---------------- prep: zero counters + c0 ----------------
__global__ void prep_kernel(const float* __restrict__ Wf, const float* __restrict__ bf) {
    for (int i = blockIdx.x * blockDim.x + threadIdx.x; i < MAXN; i += gridDim.x * blockDim.x) {
        g_deg[i] = 0; g_cursor[i] = 0;
    }
    if (blockIdx.x == 0 && threadIdx.x < H) {
        int j = threadIdx.x;
        float s = bf[j];
        #pragma unroll 8
        for (int i = 0; i < H; i++) s += Wf[i * H + j];
        g_c0[j] = s;
    }
}

// ---------------- weight prep: transpose + bf16 split ----------------
__global__ void wprep_kernel(const float* __restrict__ Wf, const float* __restrict__ Wrel,
                             const float* __restrict__ Wroot, const float* __restrict__ Wd1) {
    int m = blockIdx.x;
    const float* src;
    if (m == 0) src = Wf + H * H;
    else if (m <= 3) src = Wrel + (size_t)(m - 1) * H * H;
    else if (m <= 6) src = Wroot + (size_t)(m - 4) * H * H;
    else src = Wd1 + (size_t)(m - 7) * H * H;
    bf16* oh = g_wbh + (size_t)m * H * H;
    bf16* ol = g_wbl + (size_t)m * H * H;
    for (int i = threadIdx.x; i < H * H; i += blockDim.x) {
        int nrow = i >> 7, k = i & 127;
        float v = src[(size_t)k * H + nrow];   // transpose: store [n][k]
        bf16 h = __float2bfloat16(v);
        oh[i] = h;
        ol[i] = __float2bfloat16(v - __bfloat162float(h));
    }
}

// ---------------- edge weights ----------------
__global__ __launch_bounds__(256) void ew_kernel(const float* __restrict__ af,
                                                 const float* __restrict__ We1,
                                                 const float* __restrict__ be1,
                                                 const float* __restrict__ We2,
                                                 const float* __restrict__ be2, int E) {
    __shared__ float W1s[8 * H], b1s[H], w2s[H];
    int tid = threadIdx.x;
    for (int i = tid; i < 8 * H; i += 256) W1s[i] = We1[i];
    if (tid < H) { b1s[tid] = be1[tid]; w2s[tid] = We2[tid]; }
    __syncthreads();
    int lane = tid & 31, c = lane * 4;
    int warp = (blockIdx.x * 256 + tid) >> 5;
    int nwarp = (gridDim.x * 256) >> 5;
    float b2 = __ldg(be2);
    for (int e = warp; e < E; e += nwarp) {
        const float4* ae = (const float4*)(af + (size_t)e * 8);
        float4 a0 = __ldg(ae), a1 = __ldg(ae + 1);
        float4 acc = *(float4*)&b1s[c];
        float4 w;
        #define EW_STEP(F, AV) \
            w = *(float4*)&W1s[(F) * H + c]; \
            acc.x += (AV) * w.x; acc.y += (AV) * w.y; acc.z += (AV) * w.z; acc.w += (AV) * w.w;
        EW_STEP(0, a0.x) EW_STEP(1, a0.y) EW_STEP(2, a0.z) EW_STEP(3, a0.w)
        EW_STEP(4, a1.x) EW_STEP(5, a1.y) EW_STEP(6, a1.z) EW_STEP(7, a1.w)
        #undef EW_STEP
        acc.x = fmaxf(acc.x, 0.f); acc.y = fmaxf(acc.y, 0.f);
        acc.z = fmaxf(acc.z, 0.f); acc.w = fmaxf(acc.w, 0.f);
        float4 w2 = *(float4*)&w2s[c];
        float p = acc.x * w2.x + acc.y * w2.y + acc.z * w2.z + acc.w * w2.w;
        #pragma unroll
        for (int o = 16; o; o >>= 1) p += __shfl_xor_sync(FULLMASK, p, o);
        if (lane == 0) g_ew[e] = 1.f / (1.f + __expf(-(p + b2)));
    }
}

// ---------------- CSR build ----------------
__global__ void hist_kernel(const int* __restrict__ dst, int E) {
    for (int i = blockIdx.x * blockDim.x + threadIdx.x; i < E; i += gridDim.x * blockDim.x)
        atomicAdd(&g_deg[dst[i]], 1);
}
__global__ void scan1_kernel(int n) {
    __shared__ int s[512];
    int i = blockIdx.x * 512 + threadIdx.x;
    int v = (i < n) ? g_deg[i] : 0;
    s[threadIdx.x] = v;
    __syncthreads();
    for (int off = 1; off < 512; off <<= 1) {
        int t = (threadIdx.x >= off) ? s[threadIdx.x - off] : 0;
        __syncthreads();
        s[threadIdx.x] += t;
        __syncthreads();
    }
    if (i < n) g_rowptr[i + 1] = s[threadIdx.x];
    if (threadIdx.x == 511) g_part[blockIdx.x] = s[511];
    if (i == 0) g_rowptr[0] = 0;
}
__global__ void scan2_kernel(int nb) {
    __shared__ int s[256];
    int v = (threadIdx.x < nb) ? g_part[threadIdx.x] : 0;
    s[threadIdx.x] = v;
    __syncthreads();
    for (int off = 1; off < 256; off <<= 1) {
        int t = (threadIdx.x >= off) ? s[threadIdx.x - off] : 0;
        __syncthreads();
        s[threadIdx.x] += t;
        __syncthreads();
    }
    if (threadIdx.x < nb) g_part[threadIdx.x] = s[threadIdx.x] - v;
}
__global__ void scan3_kernel(int n) {
    for (int i = blockIdx.x * blockDim.x + threadIdx.x; i < n; i += gridDim.x * blockDim.x)
        g_rowptr[i + 1] += g_part[i >> 9];
}
__global__ void fill_kernel(const int* __restrict__ src, const int* __restrict__ dst, int E) {
    for (int i = blockIdx.x * blockDim.x + threadIdx.x; i < E; i += gridDim.x * blockDim.x) {
        int d = dst[i];
        int p = atomicAdd(&g_cursor[d], 1);
        int pos = g_rowptr[d] + p;
        g_srcs[pos] = src[i];
        g_ews[pos]  = g_ew[i];
    }
}

// ---------------- gather (atomic-free, MLP=4) ----------------
__global__ __launch_bounds__(256) void gather_kernel(int n) {
    int lane = threadIdx.x & 31, c = lane * 4;
    int warp = (blockIdx.x * 256 + threadIdx.x) >> 5;
    int nwarp = (gridDim.x * 256) >> 5;
    for (int node = warp; node < n; node += nwarp) {
        int b = __ldg(&g_rowptr[node]), e = __ldg(&g_rowptr[node + 1]);
        float4 acc = {0.f, 0.f, 0.f, 0.f};
        int t = b;
        for (; t + 4 <= e; t += 4) {
            int s0 = __ldg(&g_srcs[t + 0]), s1 = __ldg(&g_srcs[t + 1]);
            int s2 = __ldg(&g_srcs[t + 2]), s3 = __ldg(&g_srcs[t + 3]);
            float w0 = __ldg(&g_ews[t + 0]), w1 = __ldg(&g_ews[t + 1]);
            float w2 = __ldg(&g_ews[t + 2]), w3 = __ldg(&g_ews[t + 3]);
            float4 v0 = __ldg((const float4*)&g_x[(size_t)s0 * H + c]);
            float4 v1 = __ldg((const float4*)&g_x[(size_t)s1 * H + c]);
            float4 v2 = __ldg((const float4*)&g_x[(size_t)s2 * H + c]);
            float4 v3 = __ldg((const float4*)&g_x[(size_t)s3 * H + c]);
            acc.x += w0 * v0.x; acc.y += w0 * v0.y; acc.z += w0 * v0.z; acc.w += w0 * v0.w;
            acc.x += w1 * v1.x; acc.y += w1 * v1.y; acc.z += w1 * v1.z; acc.w += w1 * v1.w;
            acc.x += w2 * v2.x; acc.y += w2 * v2.y; acc.z += w2 * v2.z; acc.w += w2 * v2.w;
            acc.x += w3 * v3.x; acc.y += w3 * v3.y; acc.z += w3 * v3.z; acc.w += w3 * v3.w;
        }
        for (; t < e; t++) {
            int s = __ldg(&g_srcs[t]);
            float w = __ldg(&g_ews[t]);
            float4 v = __ldg((const float4*)&g_x[(size_t)s * H + c]);
            acc.x += w * v.x; acc.y += w * v.y; acc.z += w * v.z; acc.w += w * v.w;
        }
        *(float4*)&g_agg[(size_t)node * H + c] = acc;
    }
}

// ---------------- decoder ----------------
__global__ __launch_bounds__(256) void decoder_kernel(const int* __restrict__ src,
                                                      const int* __restrict__ dst,
                                                      const float* __restrict__ af,
                                                      const float* __restrict__ Wd1,
                                                      const float* __restrict__ bd1,
                                                      const float* __restrict__ Wd2,
                                                      const float* __restrict__ bd2,
                                                      float* __restrict__ out, int E) {
    __shared__ float Wt[8 * H], b1s[H], w2s[H];
    int tid = threadIdx.x;
    const float* Wtail = Wd1 + 2 * H * H;
    for (int i = tid; i < 8 * H; i += 256) Wt[i] = Wtail[i];
    if (tid < H) { b1s[tid] = bd1[tid]; w2s[tid] = Wd2[tid]; }
    __syncthreads();
    int lane = tid & 31, c = lane * 4;
    int warp = (blockIdx.x * 256 + tid) >> 5;
    int nwarp = (gridDim.x * 256) >> 5;
    float b2 = __ldg(bd2);
    for (int e = warp; e < E; e += nwarp) {
        int s = __ldg(&src[e]), d = __ldg(&dst[e]);
        float4 p = __ldg((const float4*)&g_P[(size_t)s * H + c]);
        float4 q = __ldg((const float4*)&g_Q[(size_t)d * H + c]);
        const float4* ae = (const float4*)(af + (size_t)e * 8);
        float4 a0 = __ldg(ae), a1 = __ldg(ae + 1);
        float4 b1 = *(float4*)&b1s[c];
        float h0 = p.x + q.x + b1.x, h1 = p.y + q.y + b1.y;
        float h2 = p.z + q.z + b1.z, h3 = p.w + q.w + b1.w;
        float4 w;
        #define DEC_STEP(F, AV) \
            w = *(float4*)&Wt[(F) * H + c]; \
            h0 += (AV) * w.x; h1 += (AV) * w.y; h2 += (AV) * w.z; h3 += (AV) * w.w;
        DEC_STEP(0, a0.x) DEC_STEP(1, a0.y) DEC_STEP(2, a0.z) DEC_STEP(3, a0.w)
        DEC_STEP(4, a1.x) DEC_STEP(5, a1.y) DEC_STEP(6, a1.z) DEC_STEP(7, a1.w)
        #undef DEC_STEP
        h0 = fmaxf(h0, 0.f); h1 = fmaxf(h1, 0.f); h2 = fmaxf(h2, 0.f); h3 = fmaxf(h3, 0.f);
        float4 w2 = *(float4*)&w2s[c];
        float part = h0 * w2.x + h1 * w2.y + h2 * w2.z + h3 * w2.w;
        #pragma unroll
        for (int o = 16; o; o >>= 1) part += __shfl_xor_sync(FULLMASK, part, o);
        if (lane == 0) out[e] = part + b2;
    }
}

// ---------------- launch ----------------
extern "C" void kernel_launch(void* const* d_in, const int* in_sizes, int n_in,
                              void* d_out, int out_size) {
    const int*   ei   = (const int*)d_in[0];
    const float* af   = (const float*)d_in[1];
    const float* hold = (const float*)d_in[2];
    int E = in_sizes[0] / 2;
    int n = in_sizes[2] / H;
    if (E > MAXE) E = MAXE;
    if (n > MAXN) n = MAXN;

    int pi = (n_in >= 19) ? 4 : 3;
    const float* Wf    = (const float*)d_in[pi + 0];
    const float* bf    = (const float*)d_in[pi + 1];
    const float* We1   = (const float*)d_in[pi + 2];
    const float* be1   = (const float*)d_in[pi + 3];
    const float* We2   = (const float*)d_in[pi + 4];
    const float* be2   = (const float*)d_in[pi + 5];
    const float* Wrel  = (const float*)d_in[pi + 6];
    const float* brel  = (const float*)d_in[pi + 7];
    const float* Wroot = (const float*)d_in[pi + 8];
    const float* gamma = (const float*)d_in[pi + 9];
    const float* beta  = (const float*)d_in[pi + 10];
    const float* Wd1   = (const float*)d_in[pi + 11];
    const float* bd1   = (const float*)d_in[pi + 12];
    const float* Wd2   = (const float*)d_in[pi + 13];
    const float* bd2   = (const float*)d_in[pi + 14];

    const int* src = ei;
    const int* dst = ei + E;

    cudaFuncSetAttribute(mm_kernel, cudaFuncAttributeMaxDynamicSharedMemorySize, MM_SMEM);

    void *xp, *aggp, *Pp, *Qp, *c0p, *whp, *wlp;
    cudaGetSymbolAddress(&xp, g_x);
    cudaGetSymbolAddress(&aggp, g_agg);
    cudaGetSymbolAddress(&Pp, g_P);
    cudaGetSymbolAddress(&Qp, g_Q);
    cudaGetSymbolAddress(&c0p, g_c0);
    cudaGetSymbolAddress(&whp, g_wbh);
    cudaGetSymbolAddress(&wlp, g_wbl);
    float* x = (float*)xp; float* agg = (float*)aggp;
    float* P = (float*)Pp; float* Q = (float*)Qp;
    float* c0 = (float*)c0p;
    bf16* wh = (bf16*)whp;
    bf16* wl = (bf16*)wlp;

    int tcg = (n + 127) / 128;
    int nb = (n + 511) / 512;

    prep_kernel<<<64, 512>>>(Wf, bf);                               // 1
    wprep_kernel<<<9, 256>>>(Wf, Wrel, Wroot, Wd1);                 // 2
    ew_kernel<<<2048, 256>>>(af, We1, be1, We2, be2, E);            // 3
    hist_kernel<<<1024, 256>>>(dst, E);                             // 4
    scan1_kernel<<<nb, 512>>>(n);                                   // 5
    // launch #6 -> ncu capture window
    mm_kernel<<<tcg, 256, MM_SMEM>>>(0, hold, nullptr,
                                     wh, wl, nullptr, nullptr,
                                     c0, nullptr, nullptr, x, n);
    scan2_kernel<<<1, 256>>>(nb);
    scan3_kernel<<<256, 256>>>(n);
    fill_kernel<<<1024, 256>>>(src, dst, E);

    for (int l = 0; l < 3; l++) {
        gather_kernel<<<6250, 256>>>(n);
        mm_kernel<<<tcg, 256, MM_SMEM>>>(1, agg, x,
                                         wh + (size_t)(1 + l) * H * H, wl + (size_t)(1 + l) * H * H,
                                         wh + (size_t)(4 + l) * H * H, wl + (size_t)(4 + l) * H * H,
                                         brel + (size_t)l * H, gamma + (size_t)l * H,
                                         beta + (size_t)l * H, x, n);
    }

    mm_kernel<<<tcg, 256, MM_SMEM>>>(3, x, nullptr,
                                     wh + (size_t)7 * H * H, wl + (size_t)7 * H * H,
                                     nullptr, nullptr, nullptr, nullptr, nullptr, P, n);
    mm_kernel<<<tcg, 256, MM_SMEM>>>(3, x, nullptr,
                                     wh + (size_t)8 * H * H, wl + (size_t)8 * H * H,
                                     nullptr, nullptr, nullptr, nullptr, nullptr, Q, n);
    decoder_kernel<<<2048, 256>>>(src, dst, af, Wd1, bd1, Wd2, bd2, (float*)d_out, E);
}